// round 6
// baseline (speedup 1.0000x reference)
#include <cuda_runtime.h>
#include <cuda_bf16.h>
#include <math.h>
#include <stdint.h>

// ---------------- problem constants ----------------
#define BB 64
#define TT 243
#define JJ 17
#define DD 256
#define DH 128
#define TR 60
#define KSEL 30
#define MROWS (BB*TT*JJ)       // 264384
#define TJ (TT*JJ)             // 4131
#define NT 2066                // ceil(MROWS/128)

// ---------------- scratch (device globals; no allocs allowed) ----------------
__device__ float g_h[(size_t)MROWS*DD];          // fp-stage output
__device__ float g_xd[(size_t)BB*TR*JJ*DD];      // pooled
__device__ float g_pm[(size_t)BB*TR*DD];         // pooled mean over J
__device__ int   g_topidx[BB*KSEL];
__device__ __nv_bfloat16 g_w0h[DD*DD], g_w0l[DD*DD];   // fp_w^T bf16 hi/lo
__device__ __nv_bfloat16 g_w1h[DD*DD], g_w1l[DD*DD];   // op_w^T bf16 hi/lo

__device__ __forceinline__ float gelu_f(float x) {
    return 0.5f * x * (1.0f + erff(x * 0.70710678118654752f));
}
__device__ __forceinline__ uint32_t smem_u32(const void* p) {
    uint32_t a;
    asm("{ .reg .u64 t; cvta.to.shared.u64 t, %1; cvt.u32.u64 %0, t; }" : "=r"(a) : "l"(p));
    return a;
}
__device__ __forceinline__ void mma_bf16(float* d, const uint32_t* a,
                                         uint32_t b0, uint32_t b1) {
    asm volatile(
        "mma.sync.aligned.m16n8k16.row.col.f32.bf16.bf16.f32 "
        "{%0,%1,%2,%3}, {%4,%5,%6,%7}, {%8,%9}, {%0,%1,%2,%3};"
        : "+f"(d[0]), "+f"(d[1]), "+f"(d[2]), "+f"(d[3])
        : "r"(a[0]), "r"(a[1]), "r"(a[2]), "r"(a[3]), "r"(b0), "r"(b1));
}
#define LDSM4(r, addr) \
    asm volatile("ldmatrix.sync.aligned.m8n8.x4.shared.b16 {%0,%1,%2,%3}, [%4];" \
        : "=r"((r)[0]), "=r"((r)[1]), "=r"((r)[2]), "=r"((r)[3]) : "r"(addr))

// smem geometry (u32 units)
#define ASTR 20                 // 16 data + 4 pad  (conflict-free LDSM)
#define A_HALF (128*ASTR)       // 2560
#define A_BUF  (2*A_HALF)       // 5120 (hi+lo for one k-chunk buffer)
#define BSTR 132                // 128 data + 4 pad
#define B_HALF (128*BSTR)       // 16896
// floats: sg 256 | sbv 256 | smu 128 | srs 128 | swl 128 | soff0 128 | soff1 128 -> 1152
#define SA_OFF 1152
#define SB_OFF (SA_OFF + 2*A_BUF)        // 11392
#define SMEM_G ((SB_OFF + 2*B_HALF) * 4) // 180736 B

// ---------------- weight prep: transpose + bf16 hi/lo split ----------------
__global__ __launch_bounds__(256) void prep_w(const float* __restrict__ W,
                                              __nv_bfloat16* __restrict__ Wh,
                                              __nv_bfloat16* __restrict__ Wl) {
    int idx = blockIdx.x * 256 + threadIdx.x;   // 65536
    int k = idx >> 8, n = idx & 255;
    float w = W[idx];                            // W[k][n]
    __nv_bfloat16 hi = __float2bfloat16(w);
    __nv_bfloat16 lo = __float2bfloat16(w - __bfloat162float(hi));
    Wh[n * DD + k] = hi;
    Wl[n * DD + k] = lo;
}

// ---------------- persistent weight-stationary bf16x3 GEMM ----------------
// MODE 0: A = LN(x_row),    out = gelu(A@W + bias)            (writes g_h)
// MODE 1: A = LN(lerp(xd)), out = gelu(A@W + bias) + x        (writes d_out)
// grid = 296: CTA bid -> n-half (bid&1), m-tiles (bid>>1, step 148).
// CTA: 512 thr, 16 warps (4M x 4N), tile 128M x 128N, warp 32x32, K chunks of 32.
template <int MODE>
__global__ __launch_bounds__(512, 1) void gemm_ws(
    const float* __restrict__ X,
    const __nv_bfloat16* __restrict__ Wh, const __nv_bfloat16* __restrict__ Wl,
    const float* __restrict__ bias,
    const float* __restrict__ ln_g, const float* __restrict__ ln_b,
    float* __restrict__ out)
{
    extern __shared__ float smem[];
    float* sg   = smem;
    float* sbv  = smem + 256;
    float* smu  = smem + 512;
    float* srs  = smem + 640;
    float* swl  = smem + 768;
    int*   soff0 = (int*)(smem + 896);
    int*   soff1 = (int*)(smem + 1024);
    uint32_t* sA = (uint32_t*)(smem + SA_OFF);
    uint32_t* sB = (uint32_t*)(smem + SB_OFF);

    const int tid  = threadIdx.x;
    const int wid  = tid >> 5;
    const int lane = tid & 31;
    const int nhalf = blockIdx.x & 1;
    const int nbase = nhalf * 128;
    const int warp_m = (wid & 3) * 32;
    const int warp_n = (wid >> 2) * 32;
    const int r  = lane >> 2;
    const int cq = lane & 3;
    const int aq = tid & 7;

    // LN params
    if (tid < 256) sg[tid] = ln_g[tid];
    else           sbv[tid - 256] = ln_b[tid - 256];

    // ---- one-time B load: this CTA's 128 n-rows, full K, hi+lo ----
    #pragma unroll
    for (int it = 0; it < 16; ++it) {
        int f = tid + it * 512;        // 0..8191
        int half = f >> 12;
        int rem = f & 4095;
        int n = rem >> 5;              // 0..127
        int q = rem & 31;              // 16B piece
        const __nv_bfloat16* src = (half ? Wl : Wh) + (size_t)(nbase + n) * DD + q * 8;
        *(uint4*)(sB + half * B_HALF + n * BSTR + q * 4) = *(const uint4*)src;
    }

    // per-thread LDSM base addresses
    const uint32_t a_u = smem_u32(sA) +
        4 * (((lane & 7) + ((lane >> 3) & 1) * 8 + warp_m) * ASTR + ((lane >> 4) & 1) * 4);
    const uint32_t b_u = smem_u32(sB) +
        4 * ((warp_n + (lane & 7) + ((lane >> 4) & 1) * 8) * BSTR + ((lane >> 3) & 1) * 4);

    const int prow = tid >> 2;      // pre-pass: 4 threads per row
    const int pseg = tid & 3;

    for (int ti = blockIdx.x >> 1; ti < NT; ti += 148) {
        const int m0 = ti * 128;

        // ---- pre-pass: per-row LN stats (+ lerp offsets for MODE 1) ----
        __syncthreads();   // previous tile done with sA/stat arrays
        {
            int m = min(m0 + prow, MROWS - 1);
            float s = 0.0f, ss = 0.0f;
            if (MODE == 0) {
                const float* p = X + (size_t)m * DD;
                #pragma unroll 4
                for (int q = 0; q < 16; ++q) {
                    float4 v4 = *(const float4*)(p + (q * 4 + pseg) * 4);
                    s  += v4.x + v4.y + v4.z + v4.w;
                    ss += v4.x*v4.x + v4.y*v4.y + v4.z*v4.z + v4.w*v4.w;
                }
                #pragma unroll
                for (int o = 1; o <= 2; o <<= 1) {
                    s  += __shfl_xor_sync(0xffffffffu, s,  o);
                    ss += __shfl_xor_sync(0xffffffffu, ss, o);
                }
                if (pseg == 0) {
                    float mu = s * (1.0f / DD);
                    float var = ss * (1.0f / DD) - mu * mu;
                    smu[prow] = mu;
                    srs[prow] = rsqrtf(var + 1e-5f);
                }
            } else {
                int b = m / TJ, rem = m % TJ;
                int t = rem / JJ, j = rem % JJ;
                float src = (t + 0.5f) * (float)(30.0 / 243.0) - 0.5f;
                src = fminf(fmaxf(src, 0.0f), (float)(KSEL - 1));
                int x0 = (int)src;
                int x1 = min(x0 + 1, KSEL - 1);
                float w = src - (float)x0;
                int i0 = g_topidx[b * KSEL + x0];
                int i1 = g_topidx[b * KSEL + x1];
                int off0 = ((b * TR + i0) * JJ + j) * DD;
                int off1 = ((b * TR + i1) * JJ + j) * DD;
                #pragma unroll 4
                for (int q = 0; q < 16; ++q) {
                    int col = (q * 4 + pseg) * 4;
                    float4 a4 = *(const float4*)(g_xd + off0 + col);
                    float4 b4 = *(const float4*)(g_xd + off1 + col);
                    float v0 = a4.x + (b4.x - a4.x) * w;
                    float v1 = a4.y + (b4.y - a4.y) * w;
                    float v2 = a4.z + (b4.z - a4.z) * w;
                    float v3 = a4.w + (b4.w - a4.w) * w;
                    s  += v0 + v1 + v2 + v3;
                    ss += v0*v0 + v1*v1 + v2*v2 + v3*v3;
                }
                #pragma unroll
                for (int o = 1; o <= 2; o <<= 1) {
                    s  += __shfl_xor_sync(0xffffffffu, s,  o);
                    ss += __shfl_xor_sync(0xffffffffu, ss, o);
                }
                if (pseg == 0) {
                    float mu = s * (1.0f / DD);
                    float var = ss * (1.0f / DD) - mu * mu;
                    smu[prow] = mu;
                    srs[prow] = rsqrtf(var + 1e-5f);
                    swl[prow] = w;
                    soff0[prow] = off0;
                    soff1[prow] = off1;
                }
            }
        }
        __syncthreads();   // stats visible; B visible (first tile)

        // per-thread row constants for A staging (2 row slots)
        int offA0[2], offA1[2];
        float muA[2], rsA[2], wA[2];
        #pragma unroll
        for (int it = 0; it < 2; ++it) {
            int row = (tid >> 3) + it * 64;
            muA[it] = smu[row];
            rsA[it] = srs[row];
            if (MODE == 0) {
                offA0[it] = min(m0 + row, MROWS - 1) * DD + aq * 4;
            } else {
                offA0[it] = soff0[row] + aq * 4;
                offA1[it] = soff1[row] + aq * 4;
                wA[it]    = swl[row];
            }
        }

        float acc[2][4][4];
        #pragma unroll
        for (int i = 0; i < 2; i++)
            #pragma unroll
            for (int j = 0; j < 4; j++)
                #pragma unroll
                for (int q = 0; q < 4; q++) acc[i][j][q] = 0.0f;

        float4 v[2];
        auto ldA = [&](int kt) {
            #pragma unroll
            for (int it = 0; it < 2; ++it) {
                if (MODE == 0) {
                    v[it] = *(const float4*)(X + offA0[it] + kt);
                } else {
                    float w = wA[it];
                    float4 a4 = *(const float4*)(g_xd + offA0[it] + kt);
                    float4 b4 = *(const float4*)(g_xd + offA1[it] + kt);
                    v[it].x = a4.x + (b4.x - a4.x) * w;
                    v[it].y = a4.y + (b4.y - a4.y) * w;
                    v[it].z = a4.z + (b4.z - a4.z) * w;
                    v[it].w = a4.w + (b4.w - a4.w) * w;
                }
            }
        };
        auto transformA = [&](int kt, int buf) {
            #pragma unroll
            for (int it = 0; it < 2; ++it) {
                int row = (tid >> 3) + it * 64;
                float4 gg = *(const float4*)(sg  + kt + aq * 4);
                float4 bb = *(const float4*)(sbv + kt + aq * 4);
                float a0 = (v[it].x - muA[it]) * rsA[it] * gg.x + bb.x;
                float a1 = (v[it].y - muA[it]) * rsA[it] * gg.y + bb.y;
                float a2 = (v[it].z - muA[it]) * rsA[it] * gg.z + bb.z;
                float a3 = (v[it].w - muA[it]) * rsA[it] * gg.w + bb.w;
                __nv_bfloat162 h01 = __floats2bfloat162_rn(a0, a1);
                __nv_bfloat162 h23 = __floats2bfloat162_rn(a2, a3);
                __nv_bfloat162 l01 = __floats2bfloat162_rn(
                    a0 - __bfloat162float(h01.x), a1 - __bfloat162float(h01.y));
                __nv_bfloat162 l23 = __floats2bfloat162_rn(
                    a2 - __bfloat162float(h23.x), a3 - __bfloat162float(h23.y));
                uint32_t base = buf * A_BUF + row * ASTR + aq * 2;
                *(uint2*)(sA + base)          = make_uint2(*(uint32_t*)&h01, *(uint32_t*)&h23);
                *(uint2*)(sA + base + A_HALF) = make_uint2(*(uint32_t*)&l01, *(uint32_t*)&l23);
            }
        };
        auto do_mma = [&](int c, int buf) {
            const uint32_t ao = a_u + 4 * (buf * A_BUF);
            const uint32_t bo = b_u + 4 * (c * 16);
            #pragma unroll
            for (int ks = 0; ks < 2; ++ks) {
                uint32_t ah[2][4], al[2][4];
                LDSM4(ah[0], ao + 4 * (ks * 8));
                LDSM4(ah[1], ao + 4 * (16 * ASTR + ks * 8));
                LDSM4(al[0], ao + 4 * (A_HALF + ks * 8));
                LDSM4(al[1], ao + 4 * (A_HALF + 16 * ASTR + ks * 8));
                #pragma unroll
                for (int p = 0; p < 2; ++p) {
                    uint32_t bh[4], bl[4];
                    LDSM4(bh, bo + 4 * (p * 16 * BSTR + ks * 8));
                    LDSM4(bl, bo + 4 * (B_HALF + p * 16 * BSTR + ks * 8));
                    const int n0 = 2 * p, n1 = 2 * p + 1;
                    mma_bf16(acc[0][n0], ah[0], bh[0], bh[1]);
                    mma_bf16(acc[1][n0], ah[1], bh[0], bh[1]);
                    mma_bf16(acc[0][n0], ah[0], bl[0], bl[1]);
                    mma_bf16(acc[1][n0], ah[1], bl[0], bl[1]);
                    mma_bf16(acc[0][n0], al[0], bh[0], bh[1]);
                    mma_bf16(acc[1][n0], al[1], bh[0], bh[1]);
                    mma_bf16(acc[0][n1], ah[0], bh[2], bh[3]);
                    mma_bf16(acc[1][n1], ah[1], bh[2], bh[3]);
                    mma_bf16(acc[0][n1], ah[0], bl[2], bl[3]);
                    mma_bf16(acc[1][n1], ah[1], bl[2], bl[3]);
                    mma_bf16(acc[0][n1], al[0], bh[2], bh[3]);
                    mma_bf16(acc[1][n1], al[1], bh[2], bh[3]);
                }
            }
        };

        // A pipeline prologue
        ldA(0);
        transformA(0, 0);
        ldA(32);
        __syncthreads();

        #pragma unroll 1
        for (int c = 0; c < 8; ++c) {
            const int buf = c & 1;
            if (wid & 1) {
                if (c < 7) transformA((c + 1) * 32, buf ^ 1);
                if (c < 6) ldA((c + 2) * 32);
                do_mma(c, buf);
            } else {
                do_mma(c, buf);
                if (c < 7) transformA((c + 1) * 32, buf ^ 1);
                if (c < 6) ldA((c + 2) * 32);
            }
            __syncthreads();
        }

        // ---- epilogue: bias + gelu (+residual) ----
        #pragma unroll
        for (int mt = 0; mt < 2; ++mt) {
            int mrow = m0 + warp_m + mt * 16 + r;
            #pragma unroll
            for (int nt = 0; nt < 4; ++nt) {
                int n = nbase + warp_n + nt * 8 + 2 * cq;
                float2 bi = *(const float2*)(bias + n);
                if (mrow < MROWS) {
                    float o0 = gelu_f(acc[mt][nt][0] + bi.x);
                    float o1 = gelu_f(acc[mt][nt][1] + bi.y);
                    if (MODE == 1) {
                        float2 xr = *(const float2*)(X + (size_t)mrow * DD + n);
                        o0 += xr.x; o1 += xr.y;
                    }
                    *(float2*)(out + (size_t)mrow * DD + n) = make_float2(o0, o1);
                }
                int m2 = mrow + 8;
                if (m2 < MROWS) {
                    float o2 = gelu_f(acc[mt][nt][2] + bi.x);
                    float o3 = gelu_f(acc[mt][nt][3] + bi.y);
                    if (MODE == 1) {
                        float2 xr = *(const float2*)(X + (size_t)m2 * DD + n);
                        o2 += xr.x; o3 += xr.y;
                    }
                    *(float2*)(out + (size_t)m2 * DD + n) = make_float2(o2, o3);
                }
            }
        }
    }
}

// ---------------- K2a: adaptive avg pool T -> T_RED ----------------
__global__ __launch_bounds__(256) void pool_kernel() {
    int id = blockIdx.x;
    int j = id % JJ;
    int r = (id / JJ) % TR;
    int b = id / (JJ * TR);
    int s = (r * TT) / TR;
    int e = ((r + 1) * TT + TR - 1) / TR;
    int c = threadIdx.x;
    float acc = 0.0f;
    for (int t = s; t < e; ++t)
        acc += g_h[((size_t)((b * TT + t) * JJ + j)) * DD + c];
    g_xd[((size_t)((b * TR + r) * JJ + j)) * DD + c] = acc / (float)(e - s);
}

// ---------------- K2b: mean over J ----------------
__global__ __launch_bounds__(256) void pooled_mean_kernel() {
    int id = blockIdx.x;
    int c = threadIdx.x;
    float acc = 0.0f;
    #pragma unroll
    for (int j = 0; j < JJ; ++j)
        acc += g_xd[((size_t)(id * JJ + j)) * DD + c];
    g_pm[(size_t)id * DD + c] = acc * (1.0f / JJ);
}

// ---------------- K3: scorer + top-k ----------------
__global__ __launch_bounds__(128) void scorer_topk(
    const float* __restrict__ w1, const float* __restrict__ b1,
    const float* __restrict__ w2, const float* __restrict__ b2)
{
    extern __shared__ float sw1[];      // [DD*DH]
    __shared__ float spm[DD];
    __shared__ float red[DH];
    __shared__ float scores[TR];
    __shared__ int   sel[TR];
    int b = blockIdx.x, tid = threadIdx.x;

    for (int i = tid; i < DD * DH; i += 128) sw1[i] = w1[i];
    float b1v = b1[tid];
    float w2v = w2[tid];
    float b2v = b2[0];
    __syncthreads();

    for (int r = 0; r < TR; ++r) {
        spm[tid]        = g_pm[((size_t)(b * TR + r)) * DD + tid];
        spm[tid + 128]  = g_pm[((size_t)(b * TR + r)) * DD + tid + 128];
        __syncthreads();
        float acc = b1v;
        #pragma unroll 8
        for (int c = 0; c < DD; ++c)
            acc = fmaf(spm[c], sw1[c * DH + tid], acc);
        red[tid] = gelu_f(acc) * w2v;
        __syncthreads();
        #pragma unroll
        for (int s = 64; s > 0; s >>= 1) {
            if (tid < s) red[tid] += red[tid + s];
            __syncthreads();
        }
        if (tid == 0)
            scores[r] = 1.0f / (1.0f + expf(-(red[0] + b2v)));
        __syncthreads();
    }
    if (tid < TR) {
        float s = scores[tid];
        int rank = 0;
        for (int q = 0; q < TR; ++q) {
            float sq = scores[q];
            rank += (sq > s) || (sq == s && q < tid);
        }
        sel[tid] = (rank < KSEL) ? 1 : 0;
    }
    __syncthreads();
    if (tid == 0) {
        int pos = 0;
        for (int r = 0; r < TR; ++r)
            if (sel[r]) g_topidx[b * KSEL + (pos++)] = r;
    }
}

// ---------------- launch ----------------
#define SMEM_SC (DD * DH * 4)   // 65536 B

extern "C" void kernel_launch(void* const* d_in, const int* in_sizes, int n_in,
                              void* d_out, int out_size) {
    const float* x       = (const float*)d_in[0];
    const float* fp_g    = (const float*)d_in[1];
    const float* fp_b    = (const float*)d_in[2];
    const float* fp_w    = (const float*)d_in[3];
    const float* fp_bias = (const float*)d_in[4];
    const float* sc_w1   = (const float*)d_in[5];
    const float* sc_b1   = (const float*)d_in[6];
    const float* sc_w2   = (const float*)d_in[7];
    const float* sc_b2   = (const float*)d_in[8];
    const float* op_g    = (const float*)d_in[9];
    const float* op_b    = (const float*)d_in[10];
    const float* op_w    = (const float*)d_in[11];
    const float* op_bias = (const float*)d_in[12];
    float* out = (float*)d_out;

    float* h_ptr;
    __nv_bfloat16 *w0h, *w0l, *w1h, *w1l;
    cudaGetSymbolAddress((void**)&h_ptr, g_h);
    cudaGetSymbolAddress((void**)&w0h, g_w0h);
    cudaGetSymbolAddress((void**)&w0l, g_w0l);
    cudaGetSymbolAddress((void**)&w1h, g_w1h);
    cudaGetSymbolAddress((void**)&w1l, g_w1l);

    cudaFuncSetAttribute(gemm_ws<0>, cudaFuncAttributeMaxDynamicSharedMemorySize, SMEM_G);
    cudaFuncSetAttribute(gemm_ws<1>, cudaFuncAttributeMaxDynamicSharedMemorySize, SMEM_G);
    cudaFuncSetAttribute(scorer_topk, cudaFuncAttributeMaxDynamicSharedMemorySize, SMEM_SC);

    prep_w<<<256, 256>>>(fp_w, w0h, w0l);
    prep_w<<<256, 256>>>(op_w, w1h, w1l);
    gemm_ws<0><<<296, 512, SMEM_G>>>(x, w0h, w0l, fp_bias, fp_g, fp_b, h_ptr);
    pool_kernel<<<BB * TR * JJ, 256>>>();
    pooled_mean_kernel<<<BB * TR, 256>>>();
    scorer_topk<<<BB, 128, SMEM_SC>>>(sc_w1, sc_b1, sc_w2, sc_b2);
    gemm_ws<1><<<296, 512, SMEM_G>>>(x, w1h, w1l, op_bias, op_g, op_b, out);
}

// round 7
// speedup vs baseline: 1.1731x; 1.1731x over previous
#include <cuda_runtime.h>
#include <cuda_bf16.h>
#include <math.h>
#include <stdint.h>

// ---------------- problem constants ----------------
#define BB 64
#define TT 243
#define JJ 17
#define DD 256
#define DH 128
#define TR 60
#define KSEL 30
#define MROWS (BB*TT*JJ)       // 264384
#define TJ (TT*JJ)             // 4131

// ---------------- scratch ----------------
__device__ float g_xd[(size_t)BB*TR*JJ*DD];      // pooled (written by GEMM0 epilogue)
__device__ float g_pm[(size_t)BB*TR*DD];         // pooled mean over J
__device__ int   g_topidx[BB*KSEL];
__device__ __nv_bfloat16 g_w0h[DD*DD], g_w0l[DD*DD];
__device__ __nv_bfloat16 g_w1h[DD*DD], g_w1l[DD*DD];

__device__ __forceinline__ float gelu_f(float x) {
    return 0.5f * x * (1.0f + erff(x * 0.70710678118654752f));
}
__device__ __forceinline__ uint32_t smem_u32(const void* p) {
    uint32_t a;
    asm("{ .reg .u64 t; cvta.to.shared.u64 t, %1; cvt.u32.u64 %0, t; }" : "=r"(a) : "l"(p));
    return a;
}
__device__ __forceinline__ void mma_bf16(float* d, const uint32_t* a,
                                         uint32_t b0, uint32_t b1) {
    asm volatile(
        "mma.sync.aligned.m16n8k16.row.col.f32.bf16.bf16.f32 "
        "{%0,%1,%2,%3}, {%4,%5,%6,%7}, {%8,%9}, {%0,%1,%2,%3};"
        : "+f"(d[0]), "+f"(d[1]), "+f"(d[2]), "+f"(d[3])
        : "r"(a[0]), "r"(a[1]), "r"(a[2]), "r"(a[3]), "r"(b0), "r"(b1));
}
#define LDSM4(r, addr) \
    asm volatile("ldmatrix.sync.aligned.m8n8.x4.shared.b16 {%0,%1,%2,%3}, [%4];" \
        : "=r"((r)[0]), "=r"((r)[1]), "=r"((r)[2]), "=r"((r)[3]) : "r"(addr))
#define CP_ASYNC(dst, src) asm volatile("cp.async.cg.shared.global [%0], [%1], 16;" :: "r"(dst), "l"(src))
#define CP_COMMIT()        asm volatile("cp.async.commit_group;" ::: "memory")
#define CP_WAIT(n)         asm volatile("cp.async.wait_group %0;" :: "n"(n) : "memory")

// smem geometry (u32 units)
#define ASTR 20            // 16 data u32 + 4 pad: conflict-free STS & LDSM
#define AB   (64*ASTR)     // 1280 per A half (hi or lo)
#define BSTR 20
#define BB_  (256*BSTR)    // 5120 per B buffer half
// header (floats): sg 256 | sbv 256 | smu 64 | srs 64 | swl 64 | soff0 64 | soff1 64
#define HDR 832
#define SMEM_G ((HDR + 2*AB + 4*BB_) * 4)   // 95488 B
#define ESTR 258           // epilogue stage stride (floats)

// ---------------- weight prep: transpose + bf16 hi/lo split ----------------
__global__ __launch_bounds__(256) void prep_w(const float* __restrict__ W,
                                              __nv_bfloat16* __restrict__ Wh,
                                              __nv_bfloat16* __restrict__ Wl) {
    int idx = blockIdx.x * 256 + threadIdx.x;
    int k = idx >> 8, n = idx & 255;
    float w = W[idx];
    __nv_bfloat16 hi = __float2bfloat16(w);
    __nv_bfloat16 lo = __float2bfloat16(w - __bfloat162float(hi));
    Wh[n * DD + k] = hi;
    Wl[n * DD + k] = lo;
}

// ---------------- fused bf16x3 mma GEMM ----------------
// MODE 0: rows = t-slab of one (b,j); A = LN(x); epilogue pools 15 bins -> g_xd
//         grid = BB*JJ*4
// MODE 1: rows = 64 consecutive m; A = LN(lerp(g_xd)); out = gelu(.)+x -> d_out
//         grid = MROWS/64
// CTA: 256 thr, 8 warps (2M x 4N), tile 64M x 256N, K chunks of 32.
template <int MODE>
__global__ __launch_bounds__(256, 2) void gemm_f(
    const float* __restrict__ X,
    const __nv_bfloat16* __restrict__ Wh, const __nv_bfloat16* __restrict__ Wl,
    const float* __restrict__ bias,
    const float* __restrict__ ln_g, const float* __restrict__ ln_b,
    float* __restrict__ out)
{
    extern __shared__ float smem[];
    float* sg  = smem;
    float* sbv = smem + 256;
    float* smu = smem + 512;
    float* srs = smem + 576;
    float* swl = smem + 640;
    int* soff0 = (int*)(smem + 704);
    int* soff1 = (int*)(smem + 768);
    uint32_t* sAh = (uint32_t*)(smem + HDR);
    uint32_t* sAl = sAh + AB;
    uint32_t* sBh = sAl + AB;          // [2][256][BSTR]
    float* sepi = smem + HDR;          // epilogue stage (MODE 0), reuses sA/sB

    const int tid  = threadIdx.x;
    const int wid  = tid >> 5;
    const int lane = tid & 31;
    const int warp_m = (wid & 1) * 32;
    const int warp_n = (wid >> 1) * 64;
    const int r  = lane >> 2;
    const int cq = lane & 3;
    const int aq = tid & 7;

    // ---- tile decode ----
    int b_ = 0, j_ = 0, ts = 0, rows = 64, r0 = 0, m0 = 0;
    if (MODE == 0) {
        int bj = blockIdx.x >> 2, tile = blockIdx.x & 3;
        b_ = bj / JJ; j_ = bj % JJ;
        r0 = tile * 15;
        ts = (r0 * TT) / TR;
        int te = ((r0 + 15) * TT + TR - 1) / TR;
        rows = te - ts;                     // 61 or 62
    } else {
        m0 = blockIdx.x * 64;
    }

    sg[tid]  = ln_g[tid];
    sbv[tid] = ln_b[tid];

    // ---- fused pre-pass: per-row LN stats (+ lerp offsets MODE 1) ----
    {
        const int prow = tid >> 2, pseg = tid & 3;
        float s = 0.0f, ss = 0.0f;
        if (MODE == 0) {
            int rc = min(prow, rows - 1);
            const float* p = X + (size_t)((b_ * TT + ts + rc) * JJ + j_) * DD;
            #pragma unroll 4
            for (int q = 0; q < 16; ++q) {
                float4 v4 = *(const float4*)(p + (q * 4 + pseg) * 4);
                s  += v4.x + v4.y + v4.z + v4.w;
                ss += v4.x*v4.x + v4.y*v4.y + v4.z*v4.z + v4.w*v4.w;
            }
            #pragma unroll
            for (int o = 1; o <= 2; o <<= 1) {
                s  += __shfl_xor_sync(0xffffffffu, s,  o);
                ss += __shfl_xor_sync(0xffffffffu, ss, o);
            }
            if (pseg == 0) {
                float mu = s * (1.0f / DD);
                float var = ss * (1.0f / DD) - mu * mu;
                smu[prow] = mu;
                srs[prow] = rsqrtf(var + 1e-5f);
            }
        } else {
            int m = m0 + prow;
            int b = m / TJ, rem = m % TJ;
            int t = rem / JJ, j = rem % JJ;
            float src = (t + 0.5f) * (float)(30.0 / 243.0) - 0.5f;
            src = fminf(fmaxf(src, 0.0f), (float)(KSEL - 1));
            int x0 = (int)src;
            int x1 = min(x0 + 1, KSEL - 1);
            float w = src - (float)x0;
            int i0 = g_topidx[b * KSEL + x0];
            int i1 = g_topidx[b * KSEL + x1];
            int off0 = ((b * TR + i0) * JJ + j) * DD;
            int off1 = ((b * TR + i1) * JJ + j) * DD;
            #pragma unroll 4
            for (int q = 0; q < 16; ++q) {
                int col = (q * 4 + pseg) * 4;
                float4 a4 = *(const float4*)(g_xd + off0 + col);
                float4 b4 = *(const float4*)(g_xd + off1 + col);
                float v0 = a4.x + (b4.x - a4.x) * w;
                float v1 = a4.y + (b4.y - a4.y) * w;
                float v2 = a4.z + (b4.z - a4.z) * w;
                float v3 = a4.w + (b4.w - a4.w) * w;
                s  += v0 + v1 + v2 + v3;
                ss += v0*v0 + v1*v1 + v2*v2 + v3*v3;
            }
            #pragma unroll
            for (int o = 1; o <= 2; o <<= 1) {
                s  += __shfl_xor_sync(0xffffffffu, s,  o);
                ss += __shfl_xor_sync(0xffffffffu, ss, o);
            }
            if (pseg == 0) {
                float mu = s * (1.0f / DD);
                float var = ss * (1.0f / DD) - mu * mu;
                smu[prow] = mu;
                srs[prow] = rsqrtf(var + 1e-5f);
                swl[prow] = w;
                soff0[prow] = off0;
                soff1[prow] = off1;
            }
        }
    }
    __syncthreads();

    // ---- per-thread A-row constants (2 slots: rows tid>>3 and +32) ----
    int offA0[2], offA1[2];
    float muA[2], rsA[2], wA[2];
    #pragma unroll
    for (int it = 0; it < 2; ++it) {
        int row = (tid >> 3) + it * 32;
        muA[it] = smu[row];
        rsA[it] = srs[row];
        if (MODE == 0) {
            int rc = min(row, rows - 1);
            offA0[it] = ((b_ * TT + ts + rc) * JJ + j_) * DD + aq * 4;
            offA1[it] = 0; wA[it] = 0.0f;
        } else {
            offA0[it] = soff0[row] + aq * 4;
            offA1[it] = soff1[row] + aq * 4;
            wA[it]    = swl[row];
        }
    }

    float acc[2][8][4];
    #pragma unroll
    for (int i = 0; i < 2; i++)
        #pragma unroll
        for (int j = 0; j < 8; j++)
            #pragma unroll
            for (int q = 0; q < 4; q++) acc[i][j][q] = 0.0f;

    // ldmatrix base addresses (layout verified in prior round)
    const uint32_t aBase = smem_u32(sAh) +
        4 * (((lane & 7) + ((lane >> 3) & 1) * 8 + warp_m) * ASTR + ((lane >> 4) & 1) * 4);
    const uint32_t bBase = smem_u32(sBh) +
        4 * ((warp_n + (lane & 7) + ((lane >> 4) & 1) * 8) * BSTR + ((lane >> 3) & 1) * 4);

    auto stageB = [&](int kt, int buf) {
        #pragma unroll
        for (int it = 0; it < 4; ++it) {
            int f = tid + it * 256;
            int n = f >> 2;
            int q = f & 3;
            uint32_t dh = smem_u32(sBh + buf * BB_ + n * BSTR + q * 4);
            CP_ASYNC(dh, Wh + (size_t)n * DD + kt + q * 8);
            uint32_t dl = smem_u32(sBh + 2 * BB_ + buf * BB_ + n * BSTR + q * 4);
            CP_ASYNC(dl, Wl + (size_t)n * DD + kt + q * 8);
        }
    };
    float4 v[2];
    auto ldA = [&](int kt) {
        #pragma unroll
        for (int it = 0; it < 2; ++it) {
            if (MODE == 0) {
                v[it] = *(const float4*)(X + offA0[it] + kt);
            } else {
                float w = wA[it];
                float4 a4 = *(const float4*)(g_xd + offA0[it] + kt);
                float4 b4 = *(const float4*)(g_xd + offA1[it] + kt);
                v[it].x = a4.x + (b4.x - a4.x) * w;
                v[it].y = a4.y + (b4.y - a4.y) * w;
                v[it].z = a4.z + (b4.z - a4.z) * w;
                v[it].w = a4.w + (b4.w - a4.w) * w;
            }
        }
    };

    stageB(0, 0);
    CP_COMMIT();
    ldA(0);

    #pragma unroll 2
    for (int c = 0; c < 8; ++c) {
        const int kt = c * 32;
        // ---- A transform + STS (v holds chunk c) ----
        #pragma unroll
        for (int it = 0; it < 2; ++it) {
            int row = (tid >> 3) + it * 32;
            float4 gg = *(const float4*)(sg  + kt + aq * 4);
            float4 bb = *(const float4*)(sbv + kt + aq * 4);
            float a0 = (v[it].x - muA[it]) * rsA[it] * gg.x + bb.x;
            float a1 = (v[it].y - muA[it]) * rsA[it] * gg.y + bb.y;
            float a2 = (v[it].z - muA[it]) * rsA[it] * gg.z + bb.z;
            float a3 = (v[it].w - muA[it]) * rsA[it] * gg.w + bb.w;
            __nv_bfloat162 h01 = __floats2bfloat162_rn(a0, a1);
            __nv_bfloat162 h23 = __floats2bfloat162_rn(a2, a3);
            __nv_bfloat162 l01 = __floats2bfloat162_rn(
                a0 - __bfloat162float(h01.x), a1 - __bfloat162float(h01.y));
            __nv_bfloat162 l23 = __floats2bfloat162_rn(
                a2 - __bfloat162float(h23.x), a3 - __bfloat162float(h23.y));
            uint32_t base = row * ASTR + aq * 2;
            *(uint2*)(sAh + base) = make_uint2(*(uint32_t*)&h01, *(uint32_t*)&h23);
            *(uint2*)(sAl + base) = make_uint2(*(uint32_t*)&l01, *(uint32_t*)&l23);
        }
        if (c < 7) { stageB(kt + 32, (c + 1) & 1); CP_COMMIT(); CP_WAIT(1); }
        else       { CP_WAIT(0); }
        __syncthreads();
        if (c < 7) ldA(kt + 32);   // hidden behind MMAs

        const int bufo = (c & 1) * BB_;
        #pragma unroll
        for (int ks = 0; ks < 2; ++ks) {
            uint32_t ah[2][4], al[2][4];
            LDSM4(ah[0], aBase + 4 * (ks * 8));
            LDSM4(ah[1], aBase + 4 * (16 * ASTR + ks * 8));
            LDSM4(al[0], aBase + 4 * (AB + ks * 8));
            LDSM4(al[1], aBase + 4 * (AB + 16 * ASTR + ks * 8));
            #pragma unroll
            for (int p = 0; p < 4; ++p) {
                uint32_t bh[4], bl[4];
                LDSM4(bh, bBase + 4 * (bufo + p * 16 * BSTR + ks * 8));
                LDSM4(bl, bBase + 4 * (2 * BB_ + bufo + p * 16 * BSTR + ks * 8));
                const int n0 = 2 * p, n1 = 2 * p + 1;
                mma_bf16(acc[0][n0], ah[0], bh[0], bh[1]);
                mma_bf16(acc[1][n0], ah[1], bh[0], bh[1]);
                mma_bf16(acc[0][n0], ah[0], bl[0], bl[1]);
                mma_bf16(acc[1][n0], ah[1], bl[0], bl[1]);
                mma_bf16(acc[0][n0], al[0], bh[0], bh[1]);
                mma_bf16(acc[1][n0], al[1], bh[0], bh[1]);
                mma_bf16(acc[0][n1], ah[0], bh[2], bh[3]);
                mma_bf16(acc[1][n1], ah[1], bh[2], bh[3]);
                mma_bf16(acc[0][n1], ah[0], bl[2], bl[3]);
                mma_bf16(acc[1][n1], ah[1], bl[2], bl[3]);
                mma_bf16(acc[0][n1], al[0], bh[2], bh[3]);
                mma_bf16(acc[1][n1], al[1], bh[2], bh[3]);
            }
        }
        __syncthreads();
    }

    // ---- epilogue ----
    if (MODE == 0) {
        // stage gelu(bias+acc) into smem, then pool 15 bins -> g_xd
        #pragma unroll
        for (int mt = 0; mt < 2; ++mt) {
            int mrow = warp_m + mt * 16 + r;
            #pragma unroll
            for (int nt = 0; nt < 8; ++nt) {
                int n = warp_n + nt * 8 + 2 * cq;
                float2 bi = *(const float2*)(bias + n);
                *(float2*)(sepi + mrow * ESTR + n) = make_float2(
                    gelu_f(acc[mt][nt][0] + bi.x), gelu_f(acc[mt][nt][1] + bi.y));
                *(float2*)(sepi + (mrow + 8) * ESTR + n) = make_float2(
                    gelu_f(acc[mt][nt][2] + bi.x), gelu_f(acc[mt][nt][3] + bi.y));
            }
        }
        __syncthreads();
        const int col = tid;
        #pragma unroll
        for (int rl = 0; rl < 15; ++rl) {
            int rg = r0 + rl;
            int s = (rg * TT) / TR - ts;
            int e = ((rg + 1) * TT + TR - 1) / TR - ts;
            float a = 0.0f;
            for (int t = s; t < e; ++t) a += sepi[t * ESTR + col];
            out[((size_t)((b_ * TR + rg) * JJ + j_)) * DD + col] = a / (float)(e - s);
        }
    } else {
        #pragma unroll
        for (int mt = 0; mt < 2; ++mt) {
            int mrow = m0 + warp_m + mt * 16 + r;
            #pragma unroll
            for (int nt = 0; nt < 8; ++nt) {
                int n = warp_n + nt * 8 + 2 * cq;
                float2 bi = *(const float2*)(bias + n);
                {
                    float2 xr = *(const float2*)(X + (size_t)mrow * DD + n);
                    *(float2*)(out + (size_t)mrow * DD + n) = make_float2(
                        gelu_f(acc[mt][nt][0] + bi.x) + xr.x,
                        gelu_f(acc[mt][nt][1] + bi.y) + xr.y);
                }
                {
                    int m2 = mrow + 8;
                    float2 xr = *(const float2*)(X + (size_t)m2 * DD + n);
                    *(float2*)(out + (size_t)m2 * DD + n) = make_float2(
                        gelu_f(acc[mt][nt][2] + bi.x) + xr.x,
                        gelu_f(acc[mt][nt][3] + bi.y) + xr.y);
                }
            }
        }
    }
}

// ---------------- pooled mean over J ----------------
__global__ __launch_bounds__(256) void pooled_mean_kernel() {
    int id = blockIdx.x;
    int c = threadIdx.x;
    float acc = 0.0f;
    #pragma unroll
    for (int j = 0; j < JJ; ++j)
        acc += g_xd[((size_t)(id * JJ + j)) * DD + c];
    g_pm[(size_t)id * DD + c] = acc * (1.0f / JJ);
}

// ---------------- scorer + top-k ----------------
__global__ __launch_bounds__(128) void scorer_topk(
    const float* __restrict__ w1, const float* __restrict__ b1,
    const float* __restrict__ w2, const float* __restrict__ b2)
{
    extern __shared__ float sw1[];      // [DD*DH]
    __shared__ float spm[DD];
    __shared__ float red[DH];
    __shared__ float scores[TR];
    __shared__ int   sel[TR];
    int b = blockIdx.x, tid = threadIdx.x;

    for (int i = tid; i < DD * DH; i += 128) sw1[i] = w1[i];
    float b1v = b1[tid];
    float w2v = w2[tid];
    float b2v = b2[0];
    __syncthreads();

    for (int r = 0; r < TR; ++r) {
        spm[tid]        = g_pm[((size_t)(b * TR + r)) * DD + tid];
        spm[tid + 128]  = g_pm[((size_t)(b * TR + r)) * DD + tid + 128];
        __syncthreads();
        float acc = b1v;
        #pragma unroll 8
        for (int c = 0; c < DD; ++c)
            acc = fmaf(spm[c], sw1[c * DH + tid], acc);
        red[tid] = gelu_f(acc) * w2v;
        __syncthreads();
        #pragma unroll
        for (int s = 64; s > 0; s >>= 1) {
            if (tid < s) red[tid] += red[tid + s];
            __syncthreads();
        }
        if (tid == 0)
            scores[r] = 1.0f / (1.0f + expf(-(red[0] + b2v)));
        __syncthreads();
    }
    if (tid < TR) {
        float s = scores[tid];
        int rank = 0;
        for (int q = 0; q < TR; ++q) {
            float sq = scores[q];
            rank += (sq > s) || (sq == s && q < tid);
        }
        sel[tid] = (rank < KSEL) ? 1 : 0;
    }
    __syncthreads();
    if (tid == 0) {
        int pos = 0;
        for (int r = 0; r < TR; ++r)
            if (sel[r]) g_topidx[b * KSEL + (pos++)] = r;
    }
}

// ---------------- launch ----------------
#define SMEM_SC (DD * DH * 4)   // 65536 B

extern "C" void kernel_launch(void* const* d_in, const int* in_sizes, int n_in,
                              void* d_out, int out_size) {
    const float* x       = (const float*)d_in[0];
    const float* fp_g    = (const float*)d_in[1];
    const float* fp_b    = (const float*)d_in[2];
    const float* fp_w    = (const float*)d_in[3];
    const float* fp_bias = (const float*)d_in[4];
    const float* sc_w1   = (const float*)d_in[5];
    const float* sc_b1   = (const float*)d_in[6];
    const float* sc_w2   = (const float*)d_in[7];
    const float* sc_b2   = (const float*)d_in[8];
    const float* op_g    = (const float*)d_in[9];
    const float* op_b    = (const float*)d_in[10];
    const float* op_w    = (const float*)d_in[11];
    const float* op_bias = (const float*)d_in[12];
    float* out = (float*)d_out;

    float* xd_ptr;
    __nv_bfloat16 *w0h, *w0l, *w1h, *w1l;
    cudaGetSymbolAddress((void**)&xd_ptr, g_xd);
    cudaGetSymbolAddress((void**)&w0h, g_w0h);
    cudaGetSymbolAddress((void**)&w0l, g_w0l);
    cudaGetSymbolAddress((void**)&w1h, g_w1h);
    cudaGetSymbolAddress((void**)&w1l, g_w1l);

    cudaFuncSetAttribute(gemm_f<0>, cudaFuncAttributeMaxDynamicSharedMemorySize, SMEM_G);
    cudaFuncSetAttribute(gemm_f<1>, cudaFuncAttributeMaxDynamicSharedMemorySize, SMEM_G);
    cudaFuncSetAttribute(scorer_topk, cudaFuncAttributeMaxDynamicSharedMemorySize, SMEM_SC);

    prep_w<<<256, 256>>>(fp_w, w0h, w0l);
    prep_w<<<256, 256>>>(op_w, w1h, w1l);
    gemm_f<0><<<BB * JJ * 4, 256, SMEM_G>>>(x, w0h, w0l, fp_bias, fp_g, fp_b, xd_ptr);
    pooled_mean_kernel<<<BB * TR, 256>>>();
    scorer_topk<<<BB, 128, SMEM_SC>>>(sc_w1, sc_b1, sc_w2, sc_b2);
    gemm_f<1><<<MROWS / 64, 256, SMEM_G>>>(x, w1h, w1l, op_bias, op_g, op_b, out);
}

// round 8
// speedup vs baseline: 1.2928x; 1.1020x over previous
#include <cuda_runtime.h>
#include <cuda_bf16.h>
#include <math.h>
#include <stdint.h>

// ---------------- problem constants ----------------
#define BB 64
#define TT 243
#define JJ 17
#define DD 256
#define DH 128
#define TR 60
#define KSEL 30
#define MROWS (BB*TT*JJ)       // 264384
#define TJ (TT*JJ)             // 4131

// ---------------- scratch ----------------
__device__ float g_xd[(size_t)BB*TR*JJ*DD];      // pooled (written by GEMM0 epilogue)
__device__ float g_pm[(size_t)BB*TR*DD];         // pooled mean over J
__device__ int   g_topidx[BB*KSEL];
__device__ __nv_bfloat16 g_w0h[DD*DD], g_w0l[DD*DD];
__device__ __nv_bfloat16 g_w1h[DD*DD], g_w1l[DD*DD];

__device__ __forceinline__ float gelu_f(float x) {
    return 0.5f * x * (1.0f + erff(x * 0.70710678118654752f));
}
__device__ __forceinline__ uint32_t smem_u32(const void* p) {
    uint32_t a;
    asm("{ .reg .u64 t; cvta.to.shared.u64 t, %1; cvt.u32.u64 %0, t; }" : "=r"(a) : "l"(p));
    return a;
}
__device__ __forceinline__ void mma_bf16(float* d, const uint32_t* a,
                                         uint32_t b0, uint32_t b1) {
    asm volatile(
        "mma.sync.aligned.m16n8k16.row.col.f32.bf16.bf16.f32 "
        "{%0,%1,%2,%3}, {%4,%5,%6,%7}, {%8,%9}, {%0,%1,%2,%3};"
        : "+f"(d[0]), "+f"(d[1]), "+f"(d[2]), "+f"(d[3])
        : "r"(a[0]), "r"(a[1]), "r"(a[2]), "r"(a[3]), "r"(b0), "r"(b1));
}
#define LDSM4(r, addr) \
    asm volatile("ldmatrix.sync.aligned.m8n8.x4.shared.b16 {%0,%1,%2,%3}, [%4];" \
        : "=r"((r)[0]), "=r"((r)[1]), "=r"((r)[2]), "=r"((r)[3]) : "r"(addr))
#define CP_ASYNC(dst, src) asm volatile("cp.async.cg.shared.global [%0], [%1], 16;" :: "r"(dst), "l"(src))
#define CP_COMMIT()        asm volatile("cp.async.commit_group;" ::: "memory")
#define CP_WAIT(n)         asm volatile("cp.async.wait_group %0;" :: "n"(n) : "memory")

// smem geometry (u32 units)
#define ASTR 20            // 16 data u32 + 4 pad
#define AB   (64*ASTR)     // 1280 per A half
#define BSTR 20
#define BB_  (256*BSTR)    // 5120 per B buffer half
// header (floats): sg 256 | sbv 256 | smu 64 | srs 64 | swl 64 | soff0 64 | soff1 64
#define HDR 832
// A: [buf][half] 4*AB ; B: [half][buf] 4*BB_
#define SMEM_G ((HDR + 4*AB + 4*BB_) * 4)   // 105728 B
#define ESTR 258           // epilogue stage stride (floats)

// ---------------- weight prep: transpose + bf16 hi/lo split ----------------
__global__ __launch_bounds__(256) void prep_w(const float* __restrict__ W,
                                              __nv_bfloat16* __restrict__ Wh,
                                              __nv_bfloat16* __restrict__ Wl) {
    int idx = blockIdx.x * 256 + threadIdx.x;
    int k = idx >> 8, n = idx & 255;
    float w = W[idx];
    __nv_bfloat16 hi = __float2bfloat16(w);
    __nv_bfloat16 lo = __float2bfloat16(w - __bfloat162float(hi));
    Wh[n * DD + k] = hi;
    Wl[n * DD + k] = lo;
}

// ---------------- fused bf16 mma GEMM ----------------
// MODE 0 (x3): rows = t-slab of one (b,j); A = LN(x); epilogue pools 15 bins -> g_xd
// MODE 1 (x2): rows = 64 consecutive m; A = LN(lerp(g_xd)); out = gelu(.)+x -> d_out
// CTA: 256 thr, 8 warps (2M x 4N), tile 64M x 256N, K chunks of 32, 1 barrier/chunk.
template <int MODE>
__global__ __launch_bounds__(256, 2) void gemm_f(
    const float* __restrict__ X,
    const __nv_bfloat16* __restrict__ Wh, const __nv_bfloat16* __restrict__ Wl,
    const float* __restrict__ bias,
    const float* __restrict__ ln_g, const float* __restrict__ ln_b,
    float* __restrict__ out)
{
    constexpr int X3 = (MODE == 0);
    extern __shared__ float smem[];
    float* sg  = smem;
    float* sbv = smem + 256;
    float* smu = smem + 512;
    float* srs = smem + 576;
    float* swl = smem + 640;
    int* soff0 = (int*)(smem + 704);
    int* soff1 = (int*)(smem + 768);
    uint32_t* sA = (uint32_t*)(smem + HDR);          // [buf][half][64][ASTR]
    uint32_t* sB = sA + 4 * AB;                       // [half][buf][256][BSTR]
    float* sepi = smem + HDR;                         // MODE 0 epilogue staging

    const int tid  = threadIdx.x;
    const int wid  = tid >> 5;
    const int lane = tid & 31;
    const int warp_m = (wid & 1) * 32;
    const int warp_n = (wid >> 1) * 64;
    const int r  = lane >> 2;
    const int cq = lane & 3;
    const int aq = tid & 7;

    // ---- tile decode ----
    int b_ = 0, j_ = 0, ts = 0, rows = 64, r0 = 0, m0 = 0;
    if (MODE == 0) {
        int bj = blockIdx.x >> 2, tile = blockIdx.x & 3;
        b_ = bj / JJ; j_ = bj % JJ;
        r0 = tile * 15;
        ts = (r0 * TT) / TR;
        int te = ((r0 + 15) * TT + TR - 1) / TR;
        rows = te - ts;                     // 61 or 62
    } else {
        m0 = blockIdx.x * 64;
    }

    sg[tid]  = ln_g[tid];
    sbv[tid] = ln_b[tid];

    // ---- fused pre-pass: per-row LN stats (+ lerp offsets MODE 1) ----
    {
        const int prow = tid >> 2, pseg = tid & 3;
        float s = 0.0f, ss = 0.0f;
        if (MODE == 0) {
            int rc = min(prow, rows - 1);
            const float* p = X + (size_t)((b_ * TT + ts + rc) * JJ + j_) * DD;
            #pragma unroll 4
            for (int q = 0; q < 16; ++q) {
                float4 v4 = *(const float4*)(p + (q * 4 + pseg) * 4);
                s  += v4.x + v4.y + v4.z + v4.w;
                ss += v4.x*v4.x + v4.y*v4.y + v4.z*v4.z + v4.w*v4.w;
            }
            #pragma unroll
            for (int o = 1; o <= 2; o <<= 1) {
                s  += __shfl_xor_sync(0xffffffffu, s,  o);
                ss += __shfl_xor_sync(0xffffffffu, ss, o);
            }
            if (pseg == 0) {
                float mu = s * (1.0f / DD);
                float var = ss * (1.0f / DD) - mu * mu;
                smu[prow] = mu;
                srs[prow] = rsqrtf(var + 1e-5f);
            }
        } else {
            int m = m0 + prow;
            int b = m / TJ, rem = m % TJ;
            int t = rem / JJ, j = rem % JJ;
            float src = (t + 0.5f) * (float)(30.0 / 243.0) - 0.5f;
            src = fminf(fmaxf(src, 0.0f), (float)(KSEL - 1));
            int x0 = (int)src;
            int x1 = min(x0 + 1, KSEL - 1);
            float w = src - (float)x0;
            int i0 = g_topidx[b * KSEL + x0];
            int i1 = g_topidx[b * KSEL + x1];
            int off0 = ((b * TR + i0) * JJ + j) * DD;
            int off1 = ((b * TR + i1) * JJ + j) * DD;
            #pragma unroll 4
            for (int q = 0; q < 16; ++q) {
                int col = (q * 4 + pseg) * 4;
                float4 a4 = *(const float4*)(g_xd + off0 + col);
                float4 b4 = *(const float4*)(g_xd + off1 + col);
                float v0 = a4.x + (b4.x - a4.x) * w;
                float v1 = a4.y + (b4.y - a4.y) * w;
                float v2 = a4.z + (b4.z - a4.z) * w;
                float v3 = a4.w + (b4.w - a4.w) * w;
                s  += v0 + v1 + v2 + v3;
                ss += v0*v0 + v1*v1 + v2*v2 + v3*v3;
            }
            #pragma unroll
            for (int o = 1; o <= 2; o <<= 1) {
                s  += __shfl_xor_sync(0xffffffffu, s,  o);
                ss += __shfl_xor_sync(0xffffffffu, ss, o);
            }
            if (pseg == 0) {
                float mu = s * (1.0f / DD);
                float var = ss * (1.0f / DD) - mu * mu;
                smu[prow] = mu;
                srs[prow] = rsqrtf(var + 1e-5f);
                swl[prow] = w;
                soff0[prow] = off0;
                soff1[prow] = off1;
            }
        }
    }
    __syncthreads();

    // ---- per-thread A-row constants (2 slots) ----
    int offA0[2], offA1[2];
    float muA[2], rsA[2], wA[2];
    #pragma unroll
    for (int it = 0; it < 2; ++it) {
        int row = (tid >> 3) + it * 32;
        muA[it] = smu[row];
        rsA[it] = srs[row];
        if (MODE == 0) {
            int rc = min(row, rows - 1);
            offA0[it] = ((b_ * TT + ts + rc) * JJ + j_) * DD + aq * 4;
            offA1[it] = 0; wA[it] = 0.0f;
        } else {
            offA0[it] = soff0[row] + aq * 4;
            offA1[it] = soff1[row] + aq * 4;
            wA[it]    = swl[row];
        }
    }

    float acc[2][8][4];
    #pragma unroll
    for (int i = 0; i < 2; i++)
        #pragma unroll
        for (int j = 0; j < 8; j++)
            #pragma unroll
            for (int q = 0; q < 4; q++) acc[i][j][q] = 0.0f;

    const uint32_t aBase = smem_u32(sA) +
        4 * (((lane & 7) + ((lane >> 3) & 1) * 8 + warp_m) * ASTR + ((lane >> 4) & 1) * 4);
    const uint32_t bBase = smem_u32(sB) +
        4 * ((warp_n + (lane & 7) + ((lane >> 4) & 1) * 8) * BSTR + ((lane >> 3) & 1) * 4);

    auto stageB = [&](int kt, int buf) {
        #pragma unroll
        for (int it = 0; it < 4; ++it) {
            int f = tid + it * 256;
            int n = f >> 2;
            int q = f & 3;
            uint32_t dh = smem_u32(sB + buf * BB_ + n * BSTR + q * 4);
            CP_ASYNC(dh, Wh + (size_t)n * DD + kt + q * 8);
            uint32_t dl = smem_u32(sB + 2 * BB_ + buf * BB_ + n * BSTR + q * 4);
            CP_ASYNC(dl, Wl + (size_t)n * DD + kt + q * 8);
        }
    };
    float4 v[2];
    auto ldA = [&](int kt) {
        #pragma unroll
        for (int it = 0; it < 2; ++it) {
            if (MODE == 0) {
                v[it] = *(const float4*)(X + offA0[it] + kt);
            } else {
                float w = wA[it];
                float4 a4 = *(const float4*)(g_xd + offA0[it] + kt);
                float4 b4 = *(const float4*)(g_xd + offA1[it] + kt);
                v[it].x = a4.x + (b4.x - a4.x) * w;
                v[it].y = a4.y + (b4.y - a4.y) * w;
                v[it].z = a4.z + (b4.z - a4.z) * w;
                v[it].w = a4.w + (b4.w - a4.w) * w;
            }
        }
    };
    auto transformA = [&](int kt, int abuf) {
        #pragma unroll
        for (int it = 0; it < 2; ++it) {
            int row = (tid >> 3) + it * 32;
            float4 gg = *(const float4*)(sg  + kt + aq * 4);
            float4 bb = *(const float4*)(sbv + kt + aq * 4);
            float a0 = (v[it].x - muA[it]) * rsA[it] * gg.x + bb.x;
            float a1 = (v[it].y - muA[it]) * rsA[it] * gg.y + bb.y;
            float a2 = (v[it].z - muA[it]) * rsA[it] * gg.z + bb.z;
            float a3 = (v[it].w - muA[it]) * rsA[it] * gg.w + bb.w;
            __nv_bfloat162 h01 = __floats2bfloat162_rn(a0, a1);
            __nv_bfloat162 h23 = __floats2bfloat162_rn(a2, a3);
            uint32_t base = abuf * 2 * AB + row * ASTR + aq * 2;
            *(uint2*)(sA + base) = make_uint2(*(uint32_t*)&h01, *(uint32_t*)&h23);
            if (X3) {
                __nv_bfloat162 l01 = __floats2bfloat162_rn(
                    a0 - __bfloat162float(h01.x), a1 - __bfloat162float(h01.y));
                __nv_bfloat162 l23 = __floats2bfloat162_rn(
                    a2 - __bfloat162float(h23.x), a3 - __bfloat162float(h23.y));
                *(uint2*)(sA + base + AB) = make_uint2(*(uint32_t*)&l01, *(uint32_t*)&l23);
            }
        }
    };
    auto do_mma = [&](int buf) {
        const uint32_t ao = aBase + 4 * (buf * 2 * AB);
        const uint32_t bo = bBase + 4 * (buf * BB_);
        #pragma unroll
        for (int ks = 0; ks < 2; ++ks) {
            uint32_t ah[2][4], al[2][4];
            LDSM4(ah[0], ao + 4 * (ks * 8));
            LDSM4(ah[1], ao + 4 * (16 * ASTR + ks * 8));
            if (X3) {
                LDSM4(al[0], ao + 4 * (AB + ks * 8));
                LDSM4(al[1], ao + 4 * (AB + 16 * ASTR + ks * 8));
            }
            #pragma unroll
            for (int p = 0; p < 4; ++p) {
                uint32_t bh[4], bl[4];
                LDSM4(bh, bo + 4 * (p * 16 * BSTR + ks * 8));
                LDSM4(bl, bo + 4 * (2 * BB_ + p * 16 * BSTR + ks * 8));
                const int n0 = 2 * p, n1 = 2 * p + 1;
                mma_bf16(acc[0][n0], ah[0], bh[0], bh[1]);
                mma_bf16(acc[1][n0], ah[1], bh[0], bh[1]);
                mma_bf16(acc[0][n0], ah[0], bl[0], bl[1]);
                mma_bf16(acc[1][n0], ah[1], bl[0], bl[1]);
                if (X3) {
                    mma_bf16(acc[0][n0], al[0], bh[0], bh[1]);
                    mma_bf16(acc[1][n0], al[1], bh[0], bh[1]);
                }
                mma_bf16(acc[0][n1], ah[0], bh[2], bh[3]);
                mma_bf16(acc[1][n1], ah[1], bh[2], bh[3]);
                mma_bf16(acc[0][n1], ah[0], bl[2], bl[3]);
                mma_bf16(acc[1][n1], ah[1], bl[2], bl[3]);
                if (X3) {
                    mma_bf16(acc[0][n1], al[0], bh[2], bh[3]);
                    mma_bf16(acc[1][n1], al[1], bh[2], bh[3]);
                }
            }
        }
    };

    // ---- prologue ----
    stageB(0, 0);
    CP_COMMIT();
    ldA(0);
    transformA(0, 0);      // Abuf0 <- chunk 0
    ldA(32);               // v <- chunk 1
    CP_WAIT(0);
    __syncthreads();

    // ---- main loop: one barrier per chunk ----
    #pragma unroll 1
    for (int c = 0; c < 8; ++c) {
        const int buf = c & 1;
        if (c < 7) { stageB((c + 1) * 32, buf ^ 1); CP_COMMIT(); }
        do_mma(buf);
        if (c < 7) transformA((c + 1) * 32, buf ^ 1);
        if (c < 6) ldA((c + 2) * 32);
        if (c < 7) CP_WAIT(0);
        __syncthreads();
    }

    // ---- epilogue ----
    if (MODE == 0) {
        #pragma unroll
        for (int mt = 0; mt < 2; ++mt) {
            int mrow = warp_m + mt * 16 + r;
            #pragma unroll
            for (int nt = 0; nt < 8; ++nt) {
                int n = warp_n + nt * 8 + 2 * cq;
                float2 bi = *(const float2*)(bias + n);
                *(float2*)(sepi + mrow * ESTR + n) = make_float2(
                    gelu_f(acc[mt][nt][0] + bi.x), gelu_f(acc[mt][nt][1] + bi.y));
                *(float2*)(sepi + (mrow + 8) * ESTR + n) = make_float2(
                    gelu_f(acc[mt][nt][2] + bi.x), gelu_f(acc[mt][nt][3] + bi.y));
            }
        }
        __syncthreads();
        const int col = tid;
        #pragma unroll
        for (int rl = 0; rl < 15; ++rl) {
            int rg = r0 + rl;
            int s = (rg * TT) / TR - ts;
            int e = ((rg + 1) * TT + TR - 1) / TR - ts;
            float a = 0.0f;
            for (int t = s; t < e; ++t) a += sepi[t * ESTR + col];
            out[((size_t)((b_ * TR + rg) * JJ + j_)) * DD + col] = a / (float)(e - s);
        }
    } else {
        #pragma unroll
        for (int mt = 0; mt < 2; ++mt) {
            int mrow = m0 + warp_m + mt * 16 + r;
            #pragma unroll
            for (int nt = 0; nt < 8; ++nt) {
                int n = warp_n + nt * 8 + 2 * cq;
                float2 bi = *(const float2*)(bias + n);
                {
                    float2 xr = *(const float2*)(X + (size_t)mrow * DD + n);
                    *(float2*)(out + (size_t)mrow * DD + n) = make_float2(
                        gelu_f(acc[mt][nt][0] + bi.x) + xr.x,
                        gelu_f(acc[mt][nt][1] + bi.y) + xr.y);
                }
                {
                    int m2 = mrow + 8;
                    float2 xr = *(const float2*)(X + (size_t)m2 * DD + n);
                    *(float2*)(out + (size_t)m2 * DD + n) = make_float2(
                        gelu_f(acc[mt][nt][2] + bi.x) + xr.x,
                        gelu_f(acc[mt][nt][3] + bi.y) + xr.y);
                }
            }
        }
    }
}

// ---------------- pooled mean over J ----------------
__global__ __launch_bounds__(256) void pooled_mean_kernel() {
    int id = blockIdx.x;
    int c = threadIdx.x;
    float acc = 0.0f;
    #pragma unroll
    for (int j = 0; j < JJ; ++j)
        acc += g_xd[((size_t)(id * JJ + j)) * DD + c];
    g_pm[(size_t)id * DD + c] = acc * (1.0f / JJ);
}

// ---------------- scorer + top-k ----------------
__global__ __launch_bounds__(128) void scorer_topk(
    const float* __restrict__ w1, const float* __restrict__ b1,
    const float* __restrict__ w2, const float* __restrict__ b2)
{
    extern __shared__ float sw1[];      // [DD*DH]
    __shared__ float spm[DD];
    __shared__ float red[DH];
    __shared__ float scores[TR];
    __shared__ int   sel[TR];
    int b = blockIdx.x, tid = threadIdx.x;

    for (int i = tid; i < DD * DH; i += 128) sw1[i] = w1[i];
    float b1v = b1[tid];
    float w2v = w2[tid];
    float b2v = b2[0];
    __syncthreads();

    for (int r = 0; r < TR; ++r) {
        spm[tid]        = g_pm[((size_t)(b * TR + r)) * DD + tid];
        spm[tid + 128]  = g_pm[((size_t)(b * TR + r)) * DD + tid + 128];
        __syncthreads();
        float acc = b1v;
        #pragma unroll 8
        for (int c = 0; c < DD; ++c)
            acc = fmaf(spm[c], sw1[c * DH + tid], acc);
        red[tid] = gelu_f(acc) * w2v;
        __syncthreads();
        #pragma unroll
        for (int s = 64; s > 0; s >>= 1) {
            if (tid < s) red[tid] += red[tid + s];
            __syncthreads();
        }
        if (tid == 0)
            scores[r] = 1.0f / (1.0f + expf(-(red[0] + b2v)));
        __syncthreads();
    }
    if (tid < TR) {
        float s = scores[tid];
        int rank = 0;
        for (int q = 0; q < TR; ++q) {
            float sq = scores[q];
            rank += (sq > s) || (sq == s && q < tid);
        }
        sel[tid] = (rank < KSEL) ? 1 : 0;
    }
    __syncthreads();
    if (tid == 0) {
        int pos = 0;
        for (int r = 0; r < TR; ++r)
            if (sel[r]) g_topidx[b * KSEL + (pos++)] = r;
    }
}

// ---------------- launch ----------------
#define SMEM_SC (DD * DH * 4)   // 65536 B

extern "C" void kernel_launch(void* const* d_in, const int* in_sizes, int n_in,
                              void* d_out, int out_size) {
    const float* x       = (const float*)d_in[0];
    const float* fp_g    = (const float*)d_in[1];
    const float* fp_b    = (const float*)d_in[2];
    const float* fp_w    = (const float*)d_in[3];
    const float* fp_bias = (const float*)d_in[4];
    const float* sc_w1   = (const float*)d_in[5];
    const float* sc_b1   = (const float*)d_in[6];
    const float* sc_w2   = (const float*)d_in[7];
    const float* sc_b2   = (const float*)d_in[8];
    const float* op_g    = (const float*)d_in[9];
    const float* op_b    = (const float*)d_in[10];
    const float* op_w    = (const float*)d_in[11];
    const float* op_bias = (const float*)d_in[12];
    float* out = (float*)d_out;

    float* xd_ptr;
    __nv_bfloat16 *w0h, *w0l, *w1h, *w1l;
    cudaGetSymbolAddress((void**)&xd_ptr, g_xd);
    cudaGetSymbolAddress((void**)&w0h, g_w0h);
    cudaGetSymbolAddress((void**)&w0l, g_w0l);
    cudaGetSymbolAddress((void**)&w1h, g_w1h);
    cudaGetSymbolAddress((void**)&w1l, g_w1l);

    cudaFuncSetAttribute(gemm_f<0>, cudaFuncAttributeMaxDynamicSharedMemorySize, SMEM_G);
    cudaFuncSetAttribute(gemm_f<1>, cudaFuncAttributeMaxDynamicSharedMemorySize, SMEM_G);
    cudaFuncSetAttribute(scorer_topk, cudaFuncAttributeMaxDynamicSharedMemorySize, SMEM_SC);

    prep_w<<<256, 256>>>(fp_w, w0h, w0l);
    prep_w<<<256, 256>>>(op_w, w1h, w1l);
    gemm_f<0><<<BB * JJ * 4, 256, SMEM_G>>>(x, w0h, w0l, fp_bias, fp_g, fp_b, xd_ptr);
    pooled_mean_kernel<<<BB * TR, 256>>>();
    scorer_topk<<<BB, 128, SMEM_SC>>>(sc_w1, sc_b1, sc_w2, sc_b2);
    gemm_f<1><<<MROWS / 64, 256, SMEM_G>>>(x, w1h, w1l, op_bias, op_g, op_b, out);
}

// round 9
// speedup vs baseline: 1.5634x; 1.2093x over previous
#include <cuda_runtime.h>
#include <cuda_bf16.h>
#include <math.h>
#include <stdint.h>

// ---------------- problem constants ----------------
#define BB 64
#define TT 243
#define JJ 17
#define DD 256
#define DH 128
#define TR 60
#define KSEL 30
#define KSJ (KSEL*JJ)          // 510
#define YROWS (BB*KSJ)         // 32640
#define MROWS (BB*TT*JJ)       // 264384
#define TJ (TT*JJ)             // 4131

// ---------------- scratch ----------------
__device__ float g_xd[(size_t)BB*TR*JJ*DD];      // pooled (GEMM0 epilogue)
__device__ float g_pm[(size_t)BB*TR*DD];         // pooled mean over J
__device__ int   g_topidx[BB*KSEL];
__device__ float g_Y[(size_t)YROWS*DD];          // xd_sel @ W1'  (33.4 MB)
__device__ float g_musel[YROWS], g_qsel[YROWS];  // mean / meansq of selected xd rows
__device__ float g_q01[BB*(KSEL-1)*JJ];          // cross E[a*b] for adjacent slots
__device__ float g_c1fp[DD], g_c2fp[DD];
__device__ float g_c1op[DD], g_c2op[DD];
__device__ __nv_bfloat16 g_w0h[DD*DD], g_w0l[DD*DD];   // (fp_g ⊙ fp_w)^T bf16 hi/lo
__device__ __nv_bfloat16 g_w1h[DD*DD], g_w1l[DD*DD];   // (op_g ⊙ op_w)^T bf16 hi/lo

__device__ __forceinline__ float gelu_f(float x) {
    return 0.5f * x * (1.0f + erff(x * 0.70710678118654752f));
}
__device__ __forceinline__ uint32_t smem_u32(const void* p) {
    uint32_t a;
    asm("{ .reg .u64 t; cvta.to.shared.u64 t, %1; cvt.u32.u64 %0, t; }" : "=r"(a) : "l"(p));
    return a;
}
__device__ __forceinline__ void mma_bf16(float* d, const uint32_t* a,
                                         uint32_t b0, uint32_t b1) {
    asm volatile(
        "mma.sync.aligned.m16n8k16.row.col.f32.bf16.bf16.f32 "
        "{%0,%1,%2,%3}, {%4,%5,%6,%7}, {%8,%9}, {%0,%1,%2,%3};"
        : "+f"(d[0]), "+f"(d[1]), "+f"(d[2]), "+f"(d[3])
        : "r"(a[0]), "r"(a[1]), "r"(a[2]), "r"(a[3]), "r"(b0), "r"(b1));
}
#define LDSM4(r, addr) \
    asm volatile("ldmatrix.sync.aligned.m8n8.x4.shared.b16 {%0,%1,%2,%3}, [%4];" \
        : "=r"((r)[0]), "=r"((r)[1]), "=r"((r)[2]), "=r"((r)[3]) : "r"(addr))
#define CP_ASYNC(dst, src) asm volatile("cp.async.cg.shared.global [%0], [%1], 16;" :: "r"(dst), "l"(src))
#define CP_COMMIT()        asm volatile("cp.async.commit_group;" ::: "memory")
#define CP_WAIT(n)         asm volatile("cp.async.wait_group %0;" :: "n"(n) : "memory")

// smem geometry (u32 units)
#define ASTR 20
#define AB   (64*ASTR)     // 1280 per A half
#define BSTR 20
#define BB_  (256*BSTR)    // 5120 per B buffer half
#define HDR 832            // c1 256 | c2 256 | smu 64 | srs 64 | pad
#define SMEM_G ((HDR + 4*AB + 4*BB_) * 4)   // 105728 B
#define ESTR 258

// ---------------- prep: W' = gamma ⊙ W, transpose + bf16 hi/lo split ----------------
__global__ __launch_bounds__(256) void prep_w(const float* __restrict__ W,
                                              const float* __restrict__ gamma,
                                              __nv_bfloat16* __restrict__ Wh,
                                              __nv_bfloat16* __restrict__ Wl) {
    int idx = blockIdx.x * 256 + threadIdx.x;
    int k = idx >> 8, n = idx & 255;
    float w = W[idx] * gamma[k];
    __nv_bfloat16 hi = __float2bfloat16(w);
    __nv_bfloat16 lo = __float2bfloat16(w - __bfloat162float(hi));
    Wh[n * DD + k] = hi;
    Wl[n * DD + k] = lo;
}

// ---------------- prep: c1[n] = beta@W + bias[n], c2[n] = gamma@W ----------------
__global__ __launch_bounds__(256) void calc_c(const float* __restrict__ W,
                                              const float* __restrict__ beta,
                                              const float* __restrict__ gamma,
                                              const float* __restrict__ bias,
                                              float* __restrict__ c1,
                                              float* __restrict__ c2) {
    __shared__ float r1[256], r2[256];
    int n = blockIdx.x, k = threadIdx.x;
    float w = W[k * DD + n];
    r1[k] = beta[k] * w;
    r2[k] = gamma[k] * w;
    __syncthreads();
    #pragma unroll
    for (int s = 128; s > 0; s >>= 1) {
        if (k < s) { r1[k] += r1[k + s]; r2[k] += r2[k + s]; }
        __syncthreads();
    }
    if (k == 0) { c1[n] = r1[0] + bias[n]; c2[n] = r2[0]; }
}

// ---------------- bf16x3 GEMM on RAW rows, affine in epilogue ----------------
// MODE 0: A = x t-slab of (b,j); epilogue gelu(affine) + pool 15 bins -> g_xd
// MODE 1: A = selected xd rows (topidx gather); plain Y store + row stats
template <int MODE>
__global__ __launch_bounds__(256, 2) void gemm_f(
    const float* __restrict__ X,
    const __nv_bfloat16* __restrict__ Wh, const __nv_bfloat16* __restrict__ Wl,
    const float* __restrict__ c1, const float* __restrict__ c2,
    float* __restrict__ out)
{
    extern __shared__ float smem[];
    float* sc1 = smem;
    float* sc2 = smem + 256;
    float* smu = smem + 512;
    float* srs = smem + 576;
    uint32_t* sA = (uint32_t*)(smem + HDR);       // [buf][half][64][ASTR]
    uint32_t* sB = sA + 4 * AB;                    // [half][buf][256][BSTR]
    float* sepi = smem + HDR;

    const int tid  = threadIdx.x;
    const int wid  = tid >> 5;
    const int lane = tid & 31;
    const int warp_m = (wid & 1) * 32;
    const int warp_n = (wid >> 1) * 64;
    const int r  = lane >> 2;
    const int cq = lane & 3;
    const int aq = tid & 7;

    int b_ = 0, j_ = 0, ts = 0, rows = 64, r0 = 0, m0 = 0;
    if (MODE == 0) {
        int bj = blockIdx.x >> 2, tile = blockIdx.x & 3;
        b_ = bj / JJ; j_ = bj % JJ;
        r0 = tile * 15;
        ts = (r0 * TT) / TR;
        int te = ((r0 + 15) * TT + TR - 1) / TR;
        rows = te - ts;
        sc1[tid] = c1[tid];
        sc2[tid] = c2[tid];
    } else {
        m0 = blockIdx.x * 64;
    }

    // per-thread A-row offsets (2 slots)
    int offA0[2];
    #pragma unroll
    for (int it = 0; it < 2; ++it) {
        int row = (tid >> 3) + it * 32;
        if (MODE == 0) {
            int rc = min(row, rows - 1);
            offA0[it] = ((b_ * TT + ts + rc) * JJ + j_) * DD + aq * 4;
        } else {
            int yrow = m0 + row;
            int b = yrow / KSJ;
            int rem = yrow % KSJ;
            int s = rem / JJ, j = rem % JJ;
            offA0[it] = ((b * TR + g_topidx[b * KSEL + s]) * JJ + j) * DD + aq * 4;
        }
    }
    float sAc[2] = {0.0f, 0.0f}, ssAc[2] = {0.0f, 0.0f};

    float acc[2][8][4];
    #pragma unroll
    for (int i = 0; i < 2; i++)
        #pragma unroll
        for (int j = 0; j < 8; j++)
            #pragma unroll
            for (int q = 0; q < 4; q++) acc[i][j][q] = 0.0f;

    const uint32_t aBase = smem_u32(sA) +
        4 * (((lane & 7) + ((lane >> 3) & 1) * 8 + warp_m) * ASTR + ((lane >> 4) & 1) * 4);
    const uint32_t bBase = smem_u32(sB) +
        4 * ((warp_n + (lane & 7) + ((lane >> 4) & 1) * 8) * BSTR + ((lane >> 3) & 1) * 4);

    auto stageB = [&](int kt, int buf) {
        #pragma unroll
        for (int it = 0; it < 4; ++it) {
            int f = tid + it * 256;
            int n = f >> 2;
            int q = f & 3;
            uint32_t dh = smem_u32(sB + buf * BB_ + n * BSTR + q * 4);
            CP_ASYNC(dh, Wh + (size_t)n * DD + kt + q * 8);
            uint32_t dl = smem_u32(sB + 2 * BB_ + buf * BB_ + n * BSTR + q * 4);
            CP_ASYNC(dl, Wl + (size_t)n * DD + kt + q * 8);
        }
    };
    const float* Asrc = (MODE == 0) ? X : &g_xd[0];
    float4 v[2];
    auto ldA = [&](int kt) {
        #pragma unroll
        for (int it = 0; it < 2; ++it)
            v[it] = *(const float4*)(Asrc + offA0[it] + kt);
    };
    auto transformA = [&](int abuf) {
        #pragma unroll
        for (int it = 0; it < 2; ++it) {
            int row = (tid >> 3) + it * 32;
            float4 vv = v[it];
            sAc[it]  += vv.x + vv.y + vv.z + vv.w;
            ssAc[it] += vv.x*vv.x + vv.y*vv.y + vv.z*vv.z + vv.w*vv.w;
            __nv_bfloat162 h01 = __floats2bfloat162_rn(vv.x, vv.y);
            __nv_bfloat162 h23 = __floats2bfloat162_rn(vv.z, vv.w);
            __nv_bfloat162 l01 = __floats2bfloat162_rn(
                vv.x - __bfloat162float(h01.x), vv.y - __bfloat162float(h01.y));
            __nv_bfloat162 l23 = __floats2bfloat162_rn(
                vv.z - __bfloat162float(h23.x), vv.w - __bfloat162float(h23.y));
            uint32_t base = abuf * 2 * AB + row * ASTR + aq * 2;
            *(uint2*)(sA + base)      = make_uint2(*(uint32_t*)&h01, *(uint32_t*)&h23);
            *(uint2*)(sA + base + AB) = make_uint2(*(uint32_t*)&l01, *(uint32_t*)&l23);
        }
    };
    auto do_mma = [&](int buf) {
        const uint32_t ao = aBase + 4 * (buf * 2 * AB);
        const uint32_t bo = bBase + 4 * (buf * BB_);
        #pragma unroll
        for (int ks = 0; ks < 2; ++ks) {
            uint32_t ah[2][4], al[2][4];
            LDSM4(ah[0], ao + 4 * (ks * 8));
            LDSM4(ah[1], ao + 4 * (16 * ASTR + ks * 8));
            LDSM4(al[0], ao + 4 * (AB + ks * 8));
            LDSM4(al[1], ao + 4 * (AB + 16 * ASTR + ks * 8));
            #pragma unroll
            for (int p = 0; p < 4; ++p) {
                uint32_t bh[4], bl[4];
                LDSM4(bh, bo + 4 * (p * 16 * BSTR + ks * 8));
                LDSM4(bl, bo + 4 * (2 * BB_ + p * 16 * BSTR + ks * 8));
                const int n0 = 2 * p, n1 = 2 * p + 1;
                mma_bf16(acc[0][n0], ah[0], bh[0], bh[1]);
                mma_bf16(acc[1][n0], ah[1], bh[0], bh[1]);
                mma_bf16(acc[0][n0], ah[0], bl[0], bl[1]);
                mma_bf16(acc[1][n0], ah[1], bl[0], bl[1]);
                mma_bf16(acc[0][n0], al[0], bh[0], bh[1]);
                mma_bf16(acc[1][n0], al[1], bh[0], bh[1]);
                mma_bf16(acc[0][n1], ah[0], bh[2], bh[3]);
                mma_bf16(acc[1][n1], ah[1], bh[2], bh[3]);
                mma_bf16(acc[0][n1], ah[0], bl[2], bl[3]);
                mma_bf16(acc[1][n1], ah[1], bl[2], bl[3]);
                mma_bf16(acc[0][n1], al[0], bh[2], bh[3]);
                mma_bf16(acc[1][n1], al[1], bh[2], bh[3]);
            }
        }
    };

    // ---- prologue ----
    stageB(0, 0);
    CP_COMMIT();
    ldA(0);
    transformA(0);
    ldA(32);
    CP_WAIT(0);
    __syncthreads();

    // ---- main loop: one barrier per chunk ----
    #pragma unroll 1
    for (int c = 0; c < 8; ++c) {
        const int buf = c & 1;
        if (c < 7) { stageB((c + 1) * 32, buf ^ 1); CP_COMMIT(); }
        do_mma(buf);
        if (c < 7) transformA(buf ^ 1);
        if (c < 6) ldA((c + 2) * 32);
        if (c < 7) CP_WAIT(0);
        __syncthreads();
    }

    // ---- finalize row stats ----
    #pragma unroll
    for (int it = 0; it < 2; ++it) {
        float s_ = sAc[it], ss_ = ssAc[it];
        #pragma unroll
        for (int o = 1; o <= 4; o <<= 1) {
            s_  += __shfl_xor_sync(0xffffffffu, s_,  o);
            ss_ += __shfl_xor_sync(0xffffffffu, ss_, o);
        }
        if (aq == 0) {
            int row = (tid >> 3) + it * 32;
            float mu = s_ * (1.0f / DD);
            float ms = ss_ * (1.0f / DD);
            if (MODE == 0) {
                smu[row] = mu;
                srs[row] = rsqrtf(ms - mu * mu + 1e-5f);
            } else {
                int yrow = m0 + row;
                g_musel[yrow] = mu;
                g_qsel[yrow]  = ms;
            }
        }
    }

    // ---- epilogue ----
    if (MODE == 0) {
        __syncthreads();
        #pragma unroll
        for (int mt = 0; mt < 2; ++mt) {
            int mrow = warp_m + mt * 16 + r;
            float muA = smu[mrow],     rsA = srs[mrow];
            float muB = smu[mrow + 8], rsB = srs[mrow + 8];
            #pragma unroll
            for (int nt = 0; nt < 8; ++nt) {
                int n = warp_n + nt * 8 + 2 * cq;
                float2 cc1 = *(float2*)(sc1 + n);
                float2 cc2 = *(float2*)(sc2 + n);
                *(float2*)(sepi + mrow * ESTR + n) = make_float2(
                    gelu_f(rsA * acc[mt][nt][0] + cc1.x - muA * rsA * cc2.x),
                    gelu_f(rsA * acc[mt][nt][1] + cc1.y - muA * rsA * cc2.y));
                *(float2*)(sepi + (mrow + 8) * ESTR + n) = make_float2(
                    gelu_f(rsB * acc[mt][nt][2] + cc1.x - muB * rsB * cc2.x),
                    gelu_f(rsB * acc[mt][nt][3] + cc1.y - muB * rsB * cc2.y));
            }
        }
        __syncthreads();
        const int col = tid;
        #pragma unroll
        for (int rl = 0; rl < 15; ++rl) {
            int rg = r0 + rl;
            int s = (rg * TT) / TR - ts;
            int e = ((rg + 1) * TT + TR - 1) / TR - ts;
            float a = 0.0f;
            for (int t = s; t < e; ++t) a += sepi[t * ESTR + col];
            out[((size_t)((b_ * TR + rg) * JJ + j_)) * DD + col] = a / (float)(e - s);
        }
    } else {
        #pragma unroll
        for (int mt = 0; mt < 2; ++mt) {
            int mrow = m0 + warp_m + mt * 16 + r;
            #pragma unroll
            for (int nt = 0; nt < 8; ++nt) {
                int n = warp_n + nt * 8 + 2 * cq;
                *(float2*)(out + (size_t)mrow * DD + n) =
                    make_float2(acc[mt][nt][0], acc[mt][nt][1]);
                *(float2*)(out + (size_t)(mrow + 8) * DD + n) =
                    make_float2(acc[mt][nt][2], acc[mt][nt][3]);
            }
        }
    }
}

// ---------------- pooled mean over J ----------------
__global__ __launch_bounds__(256) void pooled_mean_kernel() {
    int id = blockIdx.x;
    int c = threadIdx.x;
    float acc = 0.0f;
    #pragma unroll
    for (int j = 0; j < JJ; ++j)
        acc += g_xd[((size_t)(id * JJ + j)) * DD + c];
    g_pm[(size_t)id * DD + c] = acc * (1.0f / JJ);
}

// ---------------- scorer + top-k ----------------
__global__ __launch_bounds__(128) void scorer_topk(
    const float* __restrict__ w1, const float* __restrict__ b1,
    const float* __restrict__ w2, const float* __restrict__ b2)
{
    extern __shared__ float sw1[];
    __shared__ float spm[DD];
    __shared__ float red[DH];
    __shared__ float scores[TR];
    __shared__ int   sel[TR];
    int b = blockIdx.x, tid = threadIdx.x;

    for (int i = tid; i < DD * DH; i += 128) sw1[i] = w1[i];
    float b1v = b1[tid];
    float w2v = w2[tid];
    float b2v = b2[0];
    __syncthreads();

    for (int r = 0; r < TR; ++r) {
        spm[tid]        = g_pm[((size_t)(b * TR + r)) * DD + tid];
        spm[tid + 128]  = g_pm[((size_t)(b * TR + r)) * DD + tid + 128];
        __syncthreads();
        float acc = b1v;
        #pragma unroll 8
        for (int c = 0; c < DD; ++c)
            acc = fmaf(spm[c], sw1[c * DH + tid], acc);
        red[tid] = gelu_f(acc) * w2v;
        __syncthreads();
        #pragma unroll
        for (int s = 64; s > 0; s >>= 1) {
            if (tid < s) red[tid] += red[tid + s];
            __syncthreads();
        }
        if (tid == 0)
            scores[r] = 1.0f / (1.0f + expf(-(red[0] + b2v)));
        __syncthreads();
    }
    if (tid < TR) {
        float s = scores[tid];
        int rank = 0;
        for (int q = 0; q < TR; ++q) {
            float sq = scores[q];
            rank += (sq > s) || (sq == s && q < tid);
        }
        sel[tid] = (rank < KSEL) ? 1 : 0;
    }
    __syncthreads();
    if (tid == 0) {
        int pos = 0;
        for (int r = 0; r < TR; ++r)
            if (sel[r]) g_topidx[b * KSEL + (pos++)] = r;
    }
}

// ---------------- cross-dot: E[xd_sel[p] * xd_sel[p+1]] per (b, p, j) ----------------
__global__ __launch_bounds__(256) void crossdot_kernel() {
    int id = blockIdx.x * 8 + (threadIdx.x >> 5);
    int lane = threadIdx.x & 31;
    if (id >= BB * (KSEL - 1) * JJ) return;
    int j = id % JJ;
    int p = (id / JJ) % (KSEL - 1);
    int b = id / (JJ * (KSEL - 1));
    int i0 = g_topidx[b * KSEL + p];
    int i1 = g_topidx[b * KSEL + p + 1];
    const float* r0 = g_xd + (size_t)((b * TR + i0) * JJ + j) * DD;
    const float* r1 = g_xd + (size_t)((b * TR + i1) * JJ + j) * DD;
    float s = 0.0f;
    #pragma unroll
    for (int h = 0; h < 2; ++h) {
        int c = h * 128 + lane * 4;
        float4 a = *(const float4*)(r0 + c);
        float4 d = *(const float4*)(r1 + c);
        s += a.x*d.x + a.y*d.y + a.z*d.z + a.w*d.w;
    }
    #pragma unroll
    for (int o = 16; o > 0; o >>= 1)
        s += __shfl_xor_sync(0xffffffffu, s, o);
    if (lane == 0) g_q01[id] = s * (1.0f / DD);
}

// ---------------- final epilogue: lerp(Y) affine + gelu + residual ----------------
__global__ __launch_bounds__(256) void epilogue_e(const float* __restrict__ X,
                                                  float* __restrict__ out) {
    int m = blockIdx.x * 8 + (threadIdx.x >> 5);
    int lane = threadIdx.x & 31;
    int b = m / TJ, rem = m % TJ;
    int t = rem / JJ, j = rem % JJ;

    float src = (t + 0.5f) * (float)(30.0 / 243.0) - 0.5f;
    src = fminf(fmaxf(src, 0.0f), (float)(KSEL - 1));
    int x0 = (int)src;
    int x1 = min(x0 + 1, KSEL - 1);
    float w = src - (float)x0;

    int ys0 = (b * KSEL + x0) * JJ + j;
    int ys1 = (b * KSEL + x1) * JJ + j;
    float mu0 = g_musel[ys0], q0 = g_qsel[ys0];
    float mu1 = g_musel[ys1], q1 = g_qsel[ys1];
    float q01 = (x1 > x0) ? g_q01[(b * (KSEL - 1) + x0) * JJ + j] : q0;
    float iw = 1.0f - w;
    float mu = iw * mu0 + w * mu1;
    float es = iw * iw * q0 + 2.0f * w * iw * q01 + w * w * q1;
    float rs = rsqrtf(es - mu * mu + 1e-5f);
    float mrs = mu * rs;

    const float* y0 = g_Y + (size_t)ys0 * DD;
    const float* y1 = g_Y + (size_t)ys1 * DD;
    #pragma unroll
    for (int h = 0; h < 2; ++h) {
        int c = h * 128 + lane * 4;
        float4 a = *(const float4*)(y0 + c);
        float4 d = *(const float4*)(y1 + c);
        float4 cc1 = *(const float4*)(g_c1op + c);
        float4 cc2 = *(const float4*)(g_c2op + c);
        float4 xr = *(const float4*)(X + (size_t)m * DD + c);
        float4 o;
        o.x = gelu_f(rs * (a.x + (d.x - a.x) * w) + cc1.x - mrs * cc2.x) + xr.x;
        o.y = gelu_f(rs * (a.y + (d.y - a.y) * w) + cc1.y - mrs * cc2.y) + xr.y;
        o.z = gelu_f(rs * (a.z + (d.z - a.z) * w) + cc1.z - mrs * cc2.z) + xr.z;
        o.w = gelu_f(rs * (a.w + (d.w - a.w) * w) + cc1.w - mrs * cc2.w) + xr.w;
        *(float4*)(out + (size_t)m * DD + c) = o;
    }
}

// ---------------- launch ----------------
#define SMEM_SC (DD * DH * 4)

extern "C" void kernel_launch(void* const* d_in, const int* in_sizes, int n_in,
                              void* d_out, int out_size) {
    const float* x       = (const float*)d_in[0];
    const float* fp_g    = (const float*)d_in[1];
    const float* fp_b    = (const float*)d_in[2];
    const float* fp_w    = (const float*)d_in[3];
    const float* fp_bias = (const float*)d_in[4];
    const float* sc_w1   = (const float*)d_in[5];
    const float* sc_b1   = (const float*)d_in[6];
    const float* sc_w2   = (const float*)d_in[7];
    const float* sc_b2   = (const float*)d_in[8];
    const float* op_g    = (const float*)d_in[9];
    const float* op_b    = (const float*)d_in[10];
    const float* op_w    = (const float*)d_in[11];
    const float* op_bias = (const float*)d_in[12];
    float* out = (float*)d_out;

    float *xd_ptr, *y_ptr, *c1fp, *c2fp, *c1op, *c2op;
    __nv_bfloat16 *w0h, *w0l, *w1h, *w1l;
    cudaGetSymbolAddress((void**)&xd_ptr, g_xd);
    cudaGetSymbolAddress((void**)&y_ptr, g_Y);
    cudaGetSymbolAddress((void**)&c1fp, g_c1fp);
    cudaGetSymbolAddress((void**)&c2fp, g_c2fp);
    cudaGetSymbolAddress((void**)&c1op, g_c1op);
    cudaGetSymbolAddress((void**)&c2op, g_c2op);
    cudaGetSymbolAddress((void**)&w0h, g_w0h);
    cudaGetSymbolAddress((void**)&w0l, g_w0l);
    cudaGetSymbolAddress((void**)&w1h, g_w1h);
    cudaGetSymbolAddress((void**)&w1l, g_w1l);

    cudaFuncSetAttribute(gemm_f<0>, cudaFuncAttributeMaxDynamicSharedMemorySize, SMEM_G);
    cudaFuncSetAttribute(gemm_f<1>, cudaFuncAttributeMaxDynamicSharedMemorySize, SMEM_G);
    cudaFuncSetAttribute(scorer_topk, cudaFuncAttributeMaxDynamicSharedMemorySize, SMEM_SC);

    prep_w<<<256, 256>>>(fp_w, fp_g, w0h, w0l);
    prep_w<<<256, 256>>>(op_w, op_g, w1h, w1l);
    calc_c<<<256, 256>>>(fp_w, fp_b, fp_g, fp_bias, c1fp, c2fp);
    calc_c<<<256, 256>>>(op_w, op_b, op_g, op_bias, c1op, c2op);
    gemm_f<0><<<BB * JJ * 4, 256, SMEM_G>>>(x, w0h, w0l, c1fp, c2fp, xd_ptr);
    pooled_mean_kernel<<<BB * TR, 256>>>();
    scorer_topk<<<BB, 128, SMEM_SC>>>(sc_w1, sc_b1, sc_w2, sc_b2);
    gemm_f<1><<<YROWS / 64, 256, SMEM_G>>>(x, w1h, w1l, c1op, c2op, y_ptr);
    crossdot_kernel<<<(BB * (KSEL - 1) * JJ + 7) / 8, 256>>>();
    epilogue_e<<<MROWS / 8, 256>>>(x, out);
}

// round 10
// speedup vs baseline: 1.7390x; 1.1124x over previous
#include <cuda_runtime.h>
#include <cuda_bf16.h>
#include <math.h>
#include <stdint.h>

// ---------------- problem constants ----------------
#define BB 64
#define TT 243
#define JJ 17
#define DD 256
#define DH 128
#define TR 60
#define KSEL 30
#define KSJ (KSEL*JJ)          // 510
#define YROWS (BB*KSJ)         // 32640
#define MROWS (BB*TT*JJ)       // 264384
#define TJ (TT*JJ)             // 4131

// ---------------- scratch ----------------
__device__ float g_xd[(size_t)BB*TR*JJ*DD];
__device__ float g_pm[(size_t)BB*TR*DD];
__device__ float g_score[BB*TR];
__device__ int   g_topidx[BB*KSEL];
__device__ float g_Y[(size_t)YROWS*DD];
__device__ float g_musel[YROWS], g_qsel[YROWS];
__device__ float g_q01[BB*(KSEL-1)*JJ];
__device__ float g_c1fp[DD], g_c2fp[DD];
__device__ float g_c1op[DD], g_c2op[DD];
__device__ __nv_bfloat16 g_w0h[DD*DD], g_w0l[DD*DD];
__device__ __nv_bfloat16 g_w1h[DD*DD], g_w1l[DD*DD];

__device__ __forceinline__ float gelu_f(float x) {
    return 0.5f * x * (1.0f + erff(x * 0.70710678118654752f));
}
__device__ __forceinline__ uint32_t smem_u32(const void* p) {
    uint32_t a;
    asm("{ .reg .u64 t; cvta.to.shared.u64 t, %1; cvt.u32.u64 %0, t; }" : "=r"(a) : "l"(p));
    return a;
}
__device__ __forceinline__ void mma_bf16(float* d, const uint32_t* a,
                                         uint32_t b0, uint32_t b1) {
    asm volatile(
        "mma.sync.aligned.m16n8k16.row.col.f32.bf16.bf16.f32 "
        "{%0,%1,%2,%3}, {%4,%5,%6,%7}, {%8,%9}, {%0,%1,%2,%3};"
        : "+f"(d[0]), "+f"(d[1]), "+f"(d[2]), "+f"(d[3])
        : "r"(a[0]), "r"(a[1]), "r"(a[2]), "r"(a[3]), "r"(b0), "r"(b1));
}
#define LDSM4(r, addr) \
    asm volatile("ldmatrix.sync.aligned.m8n8.x4.shared.b16 {%0,%1,%2,%3}, [%4];" \
        : "=r"((r)[0]), "=r"((r)[1]), "=r"((r)[2]), "=r"((r)[3]) : "r"(addr))
#define CP_ASYNC(dst, src) asm volatile("cp.async.cg.shared.global [%0], [%1], 16;" :: "r"(dst), "l"(src))
#define CP_COMMIT()        asm volatile("cp.async.commit_group;" ::: "memory")
#define CP_WAIT(n)         asm volatile("cp.async.wait_group %0;" :: "n"(n) : "memory")

// smem geometry
#define RSTR 40                // raw A row stride (floats): conflict-free LDS
#define RAWB (64*RSTR)         // 2560 floats per raw A buffer
#define BSTR 20
#define BB_  (256*BSTR)        // 5120 u32 per B buffer half
#define HDR 832                // sc1 256 | sc2 256 | smu 64 | srs 64 | pad
#define SMEM_G ((HDR + 2*RAWB + 4*BB_) * 4)   // 105728 B
#define ESTR 258

// ---------------- prep: both weights, W' = gamma ⊙ W, transpose + bf16 hi/lo ----------------
__global__ __launch_bounds__(256) void prep_w2(
    const float* __restrict__ W0, const float* __restrict__ g0,
    const float* __restrict__ W1, const float* __restrict__ g1,
    __nv_bfloat16* __restrict__ W0h, __nv_bfloat16* __restrict__ W0l,
    __nv_bfloat16* __restrict__ W1h, __nv_bfloat16* __restrict__ W1l)
{
    int which = blockIdx.x >> 8;
    int idx = (blockIdx.x & 255) * 256 + threadIdx.x;
    int k = idx >> 8, n = idx & 255;
    const float* W = which ? W1 : W0;
    const float* g = which ? g1 : g0;
    float w = W[idx] * g[k];
    __nv_bfloat16 hi = __float2bfloat16(w);
    __nv_bfloat16 lo = __float2bfloat16(w - __bfloat162float(hi));
    (which ? W1h : W0h)[n * DD + k] = hi;
    (which ? W1l : W0l)[n * DD + k] = lo;
}

// ---------------- prep: c1[n] = beta@W + bias[n], c2[n] = gamma@W (both) ----------------
__global__ __launch_bounds__(256) void calc_c2(
    const float* __restrict__ W0, const float* __restrict__ be0,
    const float* __restrict__ ga0, const float* __restrict__ bi0,
    const float* __restrict__ W1, const float* __restrict__ be1,
    const float* __restrict__ ga1, const float* __restrict__ bi1,
    float* __restrict__ c1a, float* __restrict__ c2a,
    float* __restrict__ c1b, float* __restrict__ c2b)
{
    __shared__ float r1[256], r2[256];
    int which = blockIdx.x >> 8;
    int n = blockIdx.x & 255, k = threadIdx.x;
    const float* W = which ? W1 : W0;
    float w = W[k * DD + n];
    r1[k] = (which ? be1 : be0)[k] * w;
    r2[k] = (which ? ga1 : ga0)[k] * w;
    __syncthreads();
    #pragma unroll
    for (int s = 128; s > 0; s >>= 1) {
        if (k < s) { r1[k] += r1[k + s]; r2[k] += r2[k + s]; }
        __syncthreads();
    }
    if (k == 0) {
        (which ? c1b : c1a)[n] = r1[0] + (which ? bi1 : bi0)[n];
        (which ? c2b : c2a)[n] = r2[0];
    }
}

// ---------------- bf16 mma GEMM, A fragments built in registers ----------------
// MODE 0 (x3): A = raw x t-slab of (b,j); epilogue gelu(affine) + pool -> g_xd
// MODE 1 (x2): A = selected xd rows; plain Y store + row stats
template <int MODE>
__global__ __launch_bounds__(256, 2) void gemm_f(
    const float* __restrict__ X,
    const __nv_bfloat16* __restrict__ Wh, const __nv_bfloat16* __restrict__ Wl,
    const float* __restrict__ c1, const float* __restrict__ c2,
    float* __restrict__ out)
{
    constexpr int X3 = (MODE == 0);
    extern __shared__ float smem[];
    float* sc1 = smem;
    float* sc2 = smem + 256;
    float* smu = smem + 512;
    float* srs = smem + 576;
    float* sAr = smem + HDR;                       // [2][64][RSTR] raw fp32
    uint32_t* sB = (uint32_t*)(smem + HDR + 2 * RAWB);   // [half][buf][256][BSTR]
    float* sepi = smem + HDR;

    const int tid  = threadIdx.x;
    const int wid  = tid >> 5;
    const int lane = tid & 31;
    const int warp_m = (wid & 1) * 32;
    const int warp_n = (wid >> 1) * 64;
    const int R  = lane >> 2;
    const int cq = lane & 3;
    const int aq = tid & 7;

    int b_ = 0, j_ = 0, ts = 0, rows = 64, r0 = 0, m0 = 0;
    if (MODE == 0) {
        int bj = blockIdx.x >> 2, tile = blockIdx.x & 3;
        b_ = bj / JJ; j_ = bj % JJ;
        r0 = tile * 15;
        ts = (r0 * TT) / TR;
        int te = ((r0 + 15) * TT + TR - 1) / TR;
        rows = te - ts;
        sc1[tid] = c1[tid];
        sc2[tid] = c2[tid];
    } else {
        m0 = blockIdx.x * 64;
    }

    // staging row offsets (2 slots: rows tid>>3 and +32)
    int offA0[2];
    #pragma unroll
    for (int it = 0; it < 2; ++it) {
        int row = (tid >> 3) + it * 32;
        if (MODE == 0) {
            int rc = min(row, rows - 1);
            offA0[it] = ((b_ * TT + ts + rc) * JJ + j_) * DD + aq * 4;
        } else {
            int yrow = m0 + row;
            int b = yrow / KSJ;
            int rem = yrow % KSJ;
            int s = rem / JJ, j = rem % JJ;
            offA0[it] = ((b * TR + g_topidx[b * KSEL + s]) * JJ + j) * DD + aq * 4;
        }
    }
    const float* Asrc = (MODE == 0) ? X : &g_xd[0];
    const bool stats_on = (wid < 2);
    float sAc[4] = {0,0,0,0}, ssAc[4] = {0,0,0,0};

    float acc[2][8][4];
    #pragma unroll
    for (int i = 0; i < 2; i++)
        #pragma unroll
        for (int j = 0; j < 8; j++)
            #pragma unroll
            for (int q = 0; q < 4; q++) acc[i][j][q] = 0.0f;

    const uint32_t bBase = smem_u32(sB) +
        4 * ((warp_n + (lane & 7) + ((lane >> 4) & 1) * 8) * BSTR + ((lane >> 3) & 1) * 4);

    auto stageA = [&](int kt, int buf) {
        #pragma unroll
        for (int it = 0; it < 2; ++it) {
            int row = (tid >> 3) + it * 32;
            uint32_t d = smem_u32(sAr + buf * RAWB + row * RSTR + aq * 4);
            CP_ASYNC(d, Asrc + offA0[it] + kt);
        }
    };
    auto stageB = [&](int kt, int buf) {
        #pragma unroll
        for (int it = 0; it < 4; ++it) {
            int f = tid + it * 256;
            int n = f >> 2;
            int q = f & 3;
            uint32_t dh = smem_u32(sB + buf * BB_ + n * BSTR + q * 4);
            CP_ASYNC(dh, Wh + (size_t)n * DD + kt + q * 8);
            uint32_t dl = smem_u32(sB + 2 * BB_ + buf * BB_ + n * BSTR + q * 4);
            CP_ASYNC(dl, Wl + (size_t)n * DD + kt + q * 8);
        }
    };

    // ---- prologue ----
    stageA(0, 0); stageB(0, 0);
    CP_COMMIT();
    CP_WAIT(0);
    __syncthreads();

    // ---- main loop: one barrier per chunk ----
    #pragma unroll 1
    for (int c = 0; c < 8; ++c) {
        const int buf = c & 1;
        if (c < 7) { stageA((c + 1) * 32, buf ^ 1); stageB((c + 1) * 32, buf ^ 1); CP_COMMIT(); }

        #pragma unroll
        for (int ks = 0; ks < 2; ++ks) {
            // build A fragments (this warp's 32 rows) from raw smem
            uint32_t ah[2][4], al[2][4];
            #pragma unroll
            for (int mt = 0; mt < 2; ++mt) {
                #pragma unroll
                for (int pr = 0; pr < 2; ++pr) {
                    int row = warp_m + mt * 16 + pr * 8 + R;
                    const float* bp = sAr + buf * RAWB + row * RSTR + ks * 16 + 2 * cq;
                    float2 v0 = *(const float2*)bp;
                    float2 v1 = *(const float2*)(bp + 8);
                    if (stats_on) {
                        int sl = mt * 2 + pr;
                        sAc[sl]  += v0.x + v0.y + v1.x + v1.y;
                        ssAc[sl] += v0.x*v0.x + v0.y*v0.y + v1.x*v1.x + v1.y*v1.y;
                    }
                    __nv_bfloat162 h0 = __floats2bfloat162_rn(v0.x, v0.y);
                    __nv_bfloat162 h1 = __floats2bfloat162_rn(v1.x, v1.y);
                    ah[mt][pr]     = *(uint32_t*)&h0;
                    ah[mt][2 + pr] = *(uint32_t*)&h1;
                    if (X3) {
                        __nv_bfloat162 l0 = __floats2bfloat162_rn(
                            v0.x - __bfloat162float(h0.x), v0.y - __bfloat162float(h0.y));
                        __nv_bfloat162 l1 = __floats2bfloat162_rn(
                            v1.x - __bfloat162float(h1.x), v1.y - __bfloat162float(h1.y));
                        al[mt][pr]     = *(uint32_t*)&l0;
                        al[mt][2 + pr] = *(uint32_t*)&l1;
                    }
                }
            }
            // B fragments + MMAs
            #pragma unroll
            for (int p = 0; p < 4; ++p) {
                uint32_t bh[4], bl[4];
                LDSM4(bh, bBase + 4 * (buf * BB_ + p * 16 * BSTR + ks * 8));
                LDSM4(bl, bBase + 4 * (2 * BB_ + buf * BB_ + p * 16 * BSTR + ks * 8));
                const int n0 = 2 * p, n1 = 2 * p + 1;
                mma_bf16(acc[0][n0], ah[0], bh[0], bh[1]);
                mma_bf16(acc[1][n0], ah[1], bh[0], bh[1]);
                mma_bf16(acc[0][n0], ah[0], bl[0], bl[1]);
                mma_bf16(acc[1][n0], ah[1], bl[0], bl[1]);
                if (X3) {
                    mma_bf16(acc[0][n0], al[0], bh[0], bh[1]);
                    mma_bf16(acc[1][n0], al[1], bh[0], bh[1]);
                }
                mma_bf16(acc[0][n1], ah[0], bh[2], bh[3]);
                mma_bf16(acc[1][n1], ah[1], bh[2], bh[3]);
                mma_bf16(acc[0][n1], ah[0], bl[2], bl[3]);
                mma_bf16(acc[1][n1], ah[1], bl[2], bl[3]);
                if (X3) {
                    mma_bf16(acc[0][n1], al[0], bh[2], bh[3]);
                    mma_bf16(acc[1][n1], al[1], bh[2], bh[3]);
                }
            }
        }
        if (c < 7) CP_WAIT(0);
        __syncthreads();
    }

    // ---- finalize row stats (warps 0,1 own rows 0-63) ----
    if (stats_on) {
        #pragma unroll
        for (int sl = 0; sl < 4; ++sl) {
            float s_ = sAc[sl], ss_ = ssAc[sl];
            #pragma unroll
            for (int o = 1; o <= 2; o <<= 1) {
                s_  += __shfl_xor_sync(0xffffffffu, s_,  o);
                ss_ += __shfl_xor_sync(0xffffffffu, ss_, o);
            }
            if (cq == 0) {
                int row = warp_m + (sl >> 1) * 16 + (sl & 1) * 8 + R;
                float mu = s_ * (1.0f / DD);
                float ms = ss_ * (1.0f / DD);
                if (MODE == 0) {
                    smu[row] = mu;
                    srs[row] = rsqrtf(ms - mu * mu + 1e-5f);
                } else {
                    g_musel[m0 + row] = mu;
                    g_qsel[m0 + row]  = ms;
                }
            }
        }
    }

    // ---- epilogue ----
    if (MODE == 0) {
        __syncthreads();
        #pragma unroll
        for (int mt = 0; mt < 2; ++mt) {
            int mrow = warp_m + mt * 16 + R;
            float muA = smu[mrow],     rsA = srs[mrow];
            float muB = smu[mrow + 8], rsB = srs[mrow + 8];
            #pragma unroll
            for (int nt = 0; nt < 8; ++nt) {
                int n = warp_n + nt * 8 + 2 * cq;
                float2 cc1 = *(float2*)(sc1 + n);
                float2 cc2 = *(float2*)(sc2 + n);
                *(float2*)(sepi + mrow * ESTR + n) = make_float2(
                    gelu_f(rsA * acc[mt][nt][0] + cc1.x - muA * rsA * cc2.x),
                    gelu_f(rsA * acc[mt][nt][1] + cc1.y - muA * rsA * cc2.y));
                *(float2*)(sepi + (mrow + 8) * ESTR + n) = make_float2(
                    gelu_f(rsB * acc[mt][nt][2] + cc1.x - muB * rsB * cc2.x),
                    gelu_f(rsB * acc[mt][nt][3] + cc1.y - muB * rsB * cc2.y));
            }
        }
        __syncthreads();
        const int col = tid;
        #pragma unroll
        for (int rl = 0; rl < 15; ++rl) {
            int rg = r0 + rl;
            int s = (rg * TT) / TR - ts;
            int e = ((rg + 1) * TT + TR - 1) / TR - ts;
            float a = 0.0f;
            for (int t = s; t < e; ++t) a += sepi[t * ESTR + col];
            out[((size_t)((b_ * TR + rg) * JJ + j_)) * DD + col] = a / (float)(e - s);
        }
    } else {
        #pragma unroll
        for (int mt = 0; mt < 2; ++mt) {
            int mrow = m0 + warp_m + mt * 16 + R;
            #pragma unroll
            for (int nt = 0; nt < 8; ++nt) {
                int n = warp_n + nt * 8 + 2 * cq;
                *(float2*)(out + (size_t)mrow * DD + n) =
                    make_float2(acc[mt][nt][0], acc[mt][nt][1]);
                *(float2*)(out + (size_t)(mrow + 8) * DD + n) =
                    make_float2(acc[mt][nt][2], acc[mt][nt][3]);
            }
        }
    }
}

// ---------------- pooled mean over J ----------------
__global__ __launch_bounds__(256) void pooled_mean_kernel() {
    int id = blockIdx.x;
    int c = threadIdx.x;
    float acc = 0.0f;
    #pragma unroll
    for (int j = 0; j < JJ; ++j)
        acc += g_xd[((size_t)(id * JJ + j)) * DD + c];
    g_pm[(size_t)id * DD + c] = acc * (1.0f / JJ);
}

// ---------------- scorer: grid BB*4, each block 15 r's, w1 in smem ----------------
__global__ __launch_bounds__(128) void scorer_score(
    const float* __restrict__ w1, const float* __restrict__ b1,
    const float* __restrict__ w2, const float* __restrict__ b2)
{
    extern __shared__ float sw1[];      // [DD*DH] = 128KB
    __shared__ float spm[DD];
    __shared__ float red[DH];
    int b = blockIdx.x >> 2, grp = blockIdx.x & 3;
    int tid = threadIdx.x;

    #pragma unroll 8
    for (int i = tid; i < DD * DH / 4; i += 128)
        *(float4*)(sw1 + i * 4) = *(const float4*)(w1 + i * 4);
    float b1v = b1[tid];
    float w2v = w2[tid];
    float b2v = b2[0];
    __syncthreads();

    for (int rl = 0; rl < 15; ++rl) {
        int r = grp * 15 + rl;
        spm[tid]       = g_pm[((size_t)(b * TR + r)) * DD + tid];
        spm[tid + 128] = g_pm[((size_t)(b * TR + r)) * DD + tid + 128];
        __syncthreads();
        float acc = b1v;
        #pragma unroll 8
        for (int c = 0; c < DD; ++c)
            acc = fmaf(spm[c], sw1[c * DH + tid], acc);
        red[tid] = gelu_f(acc) * w2v;
        __syncthreads();
        #pragma unroll
        for (int s = 64; s > 0; s >>= 1) {
            if (tid < s) red[tid] += red[tid + s];
            __syncthreads();
        }
        if (tid == 0)
            g_score[b * TR + r] = 1.0f / (1.0f + expf(-(red[0] + b2v)));
        __syncthreads();
    }
}

// ---------------- top-k selection ----------------
__global__ __launch_bounds__(64) void topk_kernel() {
    __shared__ float sc[TR];
    __shared__ int sel[TR];
    int b = blockIdx.x, tid = threadIdx.x;
    if (tid < TR) sc[tid] = g_score[b * TR + tid];
    __syncthreads();
    if (tid < TR) {
        float s = sc[tid];
        int rank = 0;
        for (int q = 0; q < TR; ++q) {
            float sq = sc[q];
            rank += (sq > s) || (sq == s && q < tid);
        }
        sel[tid] = (rank < KSEL) ? 1 : 0;
    }
    __syncthreads();
    if (tid == 0) {
        int pos = 0;
        for (int r = 0; r < TR; ++r)
            if (sel[r]) g_topidx[b * KSEL + (pos++)] = r;
    }
}

// ---------------- cross-dot: E[xd_sel[p] * xd_sel[p+1]] ----------------
__global__ __launch_bounds__(256) void crossdot_kernel() {
    int id = blockIdx.x * 8 + (threadIdx.x >> 5);
    int lane = threadIdx.x & 31;
    if (id >= BB * (KSEL - 1) * JJ) return;
    int j = id % JJ;
    int p = (id / JJ) % (KSEL - 1);
    int b = id / (JJ * (KSEL - 1));
    int i0 = g_topidx[b * KSEL + p];
    int i1 = g_topidx[b * KSEL + p + 1];
    const float* r0 = g_xd + (size_t)((b * TR + i0) * JJ + j) * DD;
    const float* r1 = g_xd + (size_t)((b * TR + i1) * JJ + j) * DD;
    float s = 0.0f;
    #pragma unroll
    for (int h = 0; h < 2; ++h) {
        int c = h * 128 + lane * 4;
        float4 a = *(const float4*)(r0 + c);
        float4 d = *(const float4*)(r1 + c);
        s += a.x*d.x + a.y*d.y + a.z*d.z + a.w*d.w;
    }
    #pragma unroll
    for (int o = 16; o > 0; o >>= 1)
        s += __shfl_xor_sync(0xffffffffu, s, o);
    if (lane == 0) g_q01[id] = s * (1.0f / DD);
}

// ---------------- final epilogue: lerp(Y) affine + gelu + residual ----------------
__global__ __launch_bounds__(256) void epilogue_e(const float* __restrict__ X,
                                                  float* __restrict__ out) {
    int m = blockIdx.x * 8 + (threadIdx.x >> 5);
    int lane = threadIdx.x & 31;
    int b = m / TJ, rem = m % TJ;
    int t = rem / JJ, j = rem % JJ;

    float src = (t + 0.5f) * (float)(30.0 / 243.0) - 0.5f;
    src = fminf(fmaxf(src, 0.0f), (float)(KSEL - 1));
    int x0 = (int)src;
    int x1 = min(x0 + 1, KSEL - 1);
    float w = src - (float)x0;

    int ys0 = (b * KSEL + x0) * JJ + j;
    int ys1 = (b * KSEL + x1) * JJ + j;
    float mu0 = g_musel[ys0], q0 = g_qsel[ys0];
    float mu1 = g_musel[ys1], q1 = g_qsel[ys1];
    float q01 = (x1 > x0) ? g_q01[(b * (KSEL - 1) + x0) * JJ + j] : q0;
    float iw = 1.0f - w;
    float mu = iw * mu0 + w * mu1;
    float es = iw * iw * q0 + 2.0f * w * iw * q01 + w * w * q1;
    float rs = rsqrtf(es - mu * mu + 1e-5f);
    float mrs = mu * rs;

    const float* y0 = g_Y + (size_t)ys0 * DD;
    const float* y1 = g_Y + (size_t)ys1 * DD;
    #pragma unroll
    for (int h = 0; h < 2; ++h) {
        int c = h * 128 + lane * 4;
        float4 a = *(const float4*)(y0 + c);
        float4 d = *(const float4*)(y1 + c);
        float4 cc1 = *(const float4*)(g_c1op + c);
        float4 cc2 = *(const float4*)(g_c2op + c);
        float4 xr = *(const float4*)(X + (size_t)m * DD + c);
        float4 o;
        o.x = gelu_f(rs * (a.x + (d.x - a.x) * w) + cc1.x - mrs * cc2.x) + xr.x;
        o.y = gelu_f(rs * (a.y + (d.y - a.y) * w) + cc1.y - mrs * cc2.y) + xr.y;
        o.z = gelu_f(rs * (a.z + (d.z - a.z) * w) + cc1.z - mrs * cc2.z) + xr.z;
        o.w = gelu_f(rs * (a.w + (d.w - a.w) * w) + cc1.w - mrs * cc2.w) + xr.w;
        *(float4*)(out + (size_t)m * DD + c) = o;
    }
}

// ---------------- launch ----------------
#define SMEM_SC (DD * DH * 4)   // 131072 B

extern "C" void kernel_launch(void* const* d_in, const int* in_sizes, int n_in,
                              void* d_out, int out_size) {
    const float* x       = (const float*)d_in[0];
    const float* fp_g    = (const float*)d_in[1];
    const float* fp_b    = (const float*)d_in[2];
    const float* fp_w    = (const float*)d_in[3];
    const float* fp_bias = (const float*)d_in[4];
    const float* sc_w1   = (const float*)d_in[5];
    const float* sc_b1   = (const float*)d_in[6];
    const float* sc_w2   = (const float*)d_in[7];
    const float* sc_b2   = (const float*)d_in[8];
    const float* op_g    = (const float*)d_in[9];
    const float* op_b    = (const float*)d_in[10];
    const float* op_w    = (const float*)d_in[11];
    const float* op_bias = (const float*)d_in[12];
    float* out = (float*)d_out;

    float *xd_ptr, *y_ptr, *c1fp, *c2fp, *c1op, *c2op;
    __nv_bfloat16 *w0h, *w0l, *w1h, *w1l;
    cudaGetSymbolAddress((void**)&xd_ptr, g_xd);
    cudaGetSymbolAddress((void**)&y_ptr, g_Y);
    cudaGetSymbolAddress((void**)&c1fp, g_c1fp);
    cudaGetSymbolAddress((void**)&c2fp, g_c2fp);
    cudaGetSymbolAddress((void**)&c1op, g_c1op);
    cudaGetSymbolAddress((void**)&c2op, g_c2op);
    cudaGetSymbolAddress((void**)&w0h, g_w0h);
    cudaGetSymbolAddress((void**)&w0l, g_w0l);
    cudaGetSymbolAddress((void**)&w1h, g_w1h);
    cudaGetSymbolAddress((void**)&w1l, g_w1l);

    cudaFuncSetAttribute(gemm_f<0>, cudaFuncAttributeMaxDynamicSharedMemorySize, SMEM_G);
    cudaFuncSetAttribute(gemm_f<1>, cudaFuncAttributeMaxDynamicSharedMemorySize, SMEM_G);
    cudaFuncSetAttribute(scorer_score, cudaFuncAttributeMaxDynamicSharedMemorySize, SMEM_SC);

    prep_w2<<<512, 256>>>(fp_w, fp_g, op_w, op_g, w0h, w0l, w1h, w1l);
    calc_c2<<<512, 256>>>(fp_w, fp_b, fp_g, fp_bias, op_w, op_b, op_g, op_bias,
                          c1fp, c2fp, c1op, c2op);
    gemm_f<0><<<BB * JJ * 4, 256, SMEM_G>>>(x, w0h, w0l, c1fp, c2fp, xd_ptr);
    pooled_mean_kernel<<<BB * TR, 256>>>();
    scorer_score<<<BB * 4, 128, SMEM_SC>>>(sc_w1, sc_b1, sc_w2, sc_b2);
    topk_kernel<<<BB, 64>>>();
    gemm_f<1><<<YROWS / 64, 256, SMEM_G>>>(x, w1h, w1l, c1op, c2op, y_ptr);
    crossdot_kernel<<<(BB * (KSEL - 1) * JJ + 7) / 8, 256>>>();
    epilogue_e<<<MROWS / 8, 256>>>(x, out);
}

// round 11
// speedup vs baseline: 1.7440x; 1.0029x over previous
#include <cuda_runtime.h>
#include <cuda_bf16.h>
#include <math.h>
#include <stdint.h>

// ---------------- problem constants ----------------
#define BB 64
#define TT 243
#define JJ 17
#define DD 256
#define DH 128
#define TR 60
#define KSEL 30
#define KSJ (KSEL*JJ)          // 510
#define YROWS (BB*KSJ)         // 32640
#define MROWS (BB*TT*JJ)       // 264384
#define TJ (TT*JJ)             // 4131

// ---------------- scratch ----------------
__device__ float g_xd[(size_t)BB*TR*JJ*DD];
__device__ float g_pm[(size_t)BB*TR*DD];
__device__ float g_score[BB*TR];
__device__ int   g_topidx[BB*KSEL];
__device__ float g_Y[(size_t)YROWS*DD];
__device__ float g_musel[YROWS], g_qsel[YROWS];
__device__ float g_q01[BB*(KSEL-1)*JJ];
__device__ float g_c1fp[DD], g_c2fp[DD];
__device__ float g_c1op[DD], g_c2op[DD];
__device__ __nv_bfloat16 g_w0h[DD*DD], g_w0l[DD*DD];
__device__ __nv_bfloat16 g_w1h[DD*DD], g_w1l[DD*DD];

__device__ __forceinline__ float gelu_f(float x) {
    return 0.5f * x * (1.0f + erff(x * 0.70710678118654752f));
}
__device__ __forceinline__ uint32_t smem_u32(const void* p) {
    uint32_t a;
    asm("{ .reg .u64 t; cvta.to.shared.u64 t, %1; cvt.u32.u64 %0, t; }" : "=r"(a) : "l"(p));
    return a;
}
__device__ __forceinline__ void mma_bf16(float* d, const uint32_t* a,
                                         uint32_t b0, uint32_t b1) {
    asm volatile(
        "mma.sync.aligned.m16n8k16.row.col.f32.bf16.bf16.f32 "
        "{%0,%1,%2,%3}, {%4,%5,%6,%7}, {%8,%9}, {%0,%1,%2,%3};"
        : "+f"(d[0]), "+f"(d[1]), "+f"(d[2]), "+f"(d[3])
        : "r"(a[0]), "r"(a[1]), "r"(a[2]), "r"(a[3]), "r"(b0), "r"(b1));
}
#define LDSM4(r, addr) \
    asm volatile("ldmatrix.sync.aligned.m8n8.x4.shared.b16 {%0,%1,%2,%3}, [%4];" \
        : "=r"((r)[0]), "=r"((r)[1]), "=r"((r)[2]), "=r"((r)[3]) : "r"(addr))
#define CP_ASYNC(dst, src) asm volatile("cp.async.cg.shared.global [%0], [%1], 16;" :: "r"(dst), "l"(src))
#define CP_COMMIT()        asm volatile("cp.async.commit_group;" ::: "memory")
#define CP_WAIT(n)         asm volatile("cp.async.wait_group %0;" :: "n"(n) : "memory")

// smem geometry
#define RSTR 40
#define RAWB (64*RSTR)
#define BSTR 20
#define BB_  (256*BSTR)
#define HDR 832
#define SMEM_G ((HDR + 2*RAWB + 4*BB_) * 4)   // 105728 B
#define ESTR 258

// ---------------- prep: both weights, W' = gamma ⊙ W, transpose + bf16 hi/lo ----------------
__global__ __launch_bounds__(256) void prep_w2(
    const float* __restrict__ W0, const float* __restrict__ g0,
    const float* __restrict__ W1, const float* __restrict__ g1,
    __nv_bfloat16* __restrict__ W0h, __nv_bfloat16* __restrict__ W0l,
    __nv_bfloat16* __restrict__ W1h, __nv_bfloat16* __restrict__ W1l)
{
    int which = blockIdx.x >> 8;
    int idx = (blockIdx.x & 255) * 256 + threadIdx.x;
    int k = idx >> 8, n = idx & 255;
    const float* W = which ? W1 : W0;
    const float* g = which ? g1 : g0;
    float w = W[idx] * g[k];
    __nv_bfloat16 hi = __float2bfloat16(w);
    __nv_bfloat16 lo = __float2bfloat16(w - __bfloat162float(hi));
    (which ? W1h : W0h)[n * DD + k] = hi;
    (which ? W1l : W0l)[n * DD + k] = lo;
}

// ---------------- prep: c1[n] = beta@W + bias[n], c2[n] = gamma@W (both) ----------------
__global__ __launch_bounds__(256) void calc_c2(
    const float* __restrict__ W0, const float* __restrict__ be0,
    const float* __restrict__ ga0, const float* __restrict__ bi0,
    const float* __restrict__ W1, const float* __restrict__ be1,
    const float* __restrict__ ga1, const float* __restrict__ bi1,
    float* __restrict__ c1a, float* __restrict__ c2a,
    float* __restrict__ c1b, float* __restrict__ c2b)
{
    __shared__ float r1[256], r2[256];
    int which = blockIdx.x >> 8;
    int n = blockIdx.x & 255, k = threadIdx.x;
    const float* W = which ? W1 : W0;
    float w = W[k * DD + n];
    r1[k] = (which ? be1 : be0)[k] * w;
    r2[k] = (which ? ga1 : ga0)[k] * w;
    __syncthreads();
    #pragma unroll
    for (int s = 128; s > 0; s >>= 1) {
        if (k < s) { r1[k] += r1[k + s]; r2[k] += r2[k + s]; }
        __syncthreads();
    }
    if (k == 0) {
        (which ? c1b : c1a)[n] = r1[0] + (which ? bi1 : bi0)[n];
        (which ? c2b : c2a)[n] = r2[0];
    }
}

// ---------------- bf16 mma GEMM, A fragments in registers, chain-free MMA order ----------------
// MODE 0 (x3): A = raw x t-slab of (b,j); epilogue gelu(affine) + pool -> g_xd
// MODE 1 (x2): A = selected xd rows; plain Y store + row stats
template <int MODE>
__global__ __launch_bounds__(256, 2) void gemm_f(
    const float* __restrict__ X,
    const __nv_bfloat16* __restrict__ Wh, const __nv_bfloat16* __restrict__ Wl,
    const float* __restrict__ c1, const float* __restrict__ c2,
    float* __restrict__ out)
{
    constexpr int X3 = (MODE == 0);
    extern __shared__ float smem[];
    float* sc1 = smem;
    float* sc2 = smem + 256;
    float* smu = smem + 512;
    float* srs = smem + 576;
    float* sAr = smem + HDR;
    uint32_t* sB = (uint32_t*)(smem + HDR + 2 * RAWB);
    float* sepi = smem + HDR;

    const int tid  = threadIdx.x;
    const int wid  = tid >> 5;
    const int lane = tid & 31;
    const int warp_m = (wid & 1) * 32;
    const int warp_n = (wid >> 1) * 64;
    const int R  = lane >> 2;
    const int cq = lane & 3;
    const int aq = tid & 7;

    int b_ = 0, j_ = 0, ts = 0, rows = 64, r0 = 0, m0 = 0;
    if (MODE == 0) {
        int bj = blockIdx.x >> 2, tile = blockIdx.x & 3;
        b_ = bj / JJ; j_ = bj % JJ;
        r0 = tile * 15;
        ts = (r0 * TT) / TR;
        int te = ((r0 + 15) * TT + TR - 1) / TR;
        rows = te - ts;
        sc1[tid] = c1[tid];
        sc2[tid] = c2[tid];
    } else {
        m0 = blockIdx.x * 64;
    }

    int offA0[2];
    #pragma unroll
    for (int it = 0; it < 2; ++it) {
        int row = (tid >> 3) + it * 32;
        if (MODE == 0) {
            int rc = min(row, rows - 1);
            offA0[it] = ((b_ * TT + ts + rc) * JJ + j_) * DD + aq * 4;
        } else {
            int yrow = m0 + row;
            int b = yrow / KSJ;
            int rem = yrow % KSJ;
            int s = rem / JJ, j = rem % JJ;
            offA0[it] = ((b * TR + g_topidx[b * KSEL + s]) * JJ + j) * DD + aq * 4;
        }
    }
    const float* Asrc = (MODE == 0) ? X : &g_xd[0];
    const bool stats_on = (wid < 2);
    float sAc[4] = {0,0,0,0}, ssAc[4] = {0,0,0,0};

    float acc[2][8][4];
    #pragma unroll
    for (int i = 0; i < 2; i++)
        #pragma unroll
        for (int j = 0; j < 8; j++)
            #pragma unroll
            for (int q = 0; q < 4; q++) acc[i][j][q] = 0.0f;

    const uint32_t bBase = smem_u32(sB) +
        4 * ((warp_n + (lane & 7) + ((lane >> 4) & 1) * 8) * BSTR + ((lane >> 3) & 1) * 4);

    auto stageA = [&](int kt, int buf) {
        #pragma unroll
        for (int it = 0; it < 2; ++it) {
            int row = (tid >> 3) + it * 32;
            uint32_t d = smem_u32(sAr + buf * RAWB + row * RSTR + aq * 4);
            CP_ASYNC(d, Asrc + offA0[it] + kt);
        }
    };
    auto stageB = [&](int kt, int buf) {
        #pragma unroll
        for (int it = 0; it < 4; ++it) {
            int f = tid + it * 256;
            int n = f >> 2;
            int q = f & 3;
            uint32_t dh = smem_u32(sB + buf * BB_ + n * BSTR + q * 4);
            CP_ASYNC(dh, Wh + (size_t)n * DD + kt + q * 8);
            uint32_t dl = smem_u32(sB + 2 * BB_ + buf * BB_ + n * BSTR + q * 4);
            CP_ASYNC(dl, Wl + (size_t)n * DD + kt + q * 8);
        }
    };

    // ---- prologue ----
    stageA(0, 0); stageB(0, 0);
    CP_COMMIT();
    CP_WAIT(0);
    __syncthreads();

    // ---- main loop ----
    #pragma unroll 1
    for (int c = 0; c < 8; ++c) {
        const int buf = c & 1;
        if (c < 7) { stageA((c + 1) * 32, buf ^ 1); stageB((c + 1) * 32, buf ^ 1); CP_COMMIT(); }

        #pragma unroll
        for (int ks = 0; ks < 2; ++ks) {
            // build A fragments from raw smem
            uint32_t ah[2][4], al[2][4];
            #pragma unroll
            for (int mt = 0; mt < 2; ++mt) {
                #pragma unroll
                for (int pr = 0; pr < 2; ++pr) {
                    int row = warp_m + mt * 16 + pr * 8 + R;
                    const float* bp = sAr + buf * RAWB + row * RSTR + ks * 16 + 2 * cq;
                    float2 v0 = *(const float2*)bp;
                    float2 v1 = *(const float2*)(bp + 8);
                    if (stats_on) {
                        int sl = mt * 2 + pr;
                        sAc[sl]  += v0.x + v0.y + v1.x + v1.y;
                        ssAc[sl] += v0.x*v0.x + v0.y*v0.y + v1.x*v1.x + v1.y*v1.y;
                    }
                    __nv_bfloat162 h0 = __floats2bfloat162_rn(v0.x, v0.y);
                    __nv_bfloat162 h1 = __floats2bfloat162_rn(v1.x, v1.y);
                    ah[mt][pr]     = *(uint32_t*)&h0;
                    ah[mt][2 + pr] = *(uint32_t*)&h1;
                    if (X3) {
                        __nv_bfloat162 l0 = __floats2bfloat162_rn(
                            v0.x - __bfloat162float(h0.x), v0.y - __bfloat162float(h0.y));
                        __nv_bfloat162 l1 = __floats2bfloat162_rn(
                            v1.x - __bfloat162float(h1.x), v1.y - __bfloat162float(h1.y));
                        al[mt][pr]     = *(uint32_t*)&l0;
                        al[mt][2 + pr] = *(uint32_t*)&l1;
                    }
                }
            }
            // B fragments + MMAs (term-major order: no back-to-back same-acc MMAs)
            #pragma unroll
            for (int p = 0; p < 4; ++p) {
                uint32_t bh[4], bl[4];
                LDSM4(bh, bBase + 4 * (buf * BB_ + p * 16 * BSTR + ks * 8));
                LDSM4(bl, bBase + 4 * (2 * BB_ + buf * BB_ + p * 16 * BSTR + ks * 8));
                const int n0 = 2 * p, n1 = 2 * p + 1;
                // hi*hi
                mma_bf16(acc[0][n0], ah[0], bh[0], bh[1]);
                mma_bf16(acc[1][n0], ah[1], bh[0], bh[1]);
                mma_bf16(acc[0][n1], ah[0], bh[2], bh[3]);
                mma_bf16(acc[1][n1], ah[1], bh[2], bh[3]);
                // hi*lo
                mma_bf16(acc[0][n0], ah[0], bl[0], bl[1]);
                mma_bf16(acc[1][n0], ah[1], bl[0], bl[1]);
                mma_bf16(acc[0][n1], ah[0], bl[2], bl[3]);
                mma_bf16(acc[1][n1], ah[1], bl[2], bl[3]);
                if (X3) {
                    // lo*hi
                    mma_bf16(acc[0][n0], al[0], bh[0], bh[1]);
                    mma_bf16(acc[1][n0], al[1], bh[0], bh[1]);
                    mma_bf16(acc[0][n1], al[0], bh[2], bh[3]);
                    mma_bf16(acc[1][n1], al[1], bh[2], bh[3]);
                }
            }
        }
        if (c < 7) CP_WAIT(0);
        __syncthreads();
    }

    // ---- finalize row stats (warps 0,1 own rows 0-63) ----
    if (stats_on) {
        #pragma unroll
        for (int sl = 0; sl < 4; ++sl) {
            float s_ = sAc[sl], ss_ = ssAc[sl];
            #pragma unroll
            for (int o = 1; o <= 2; o <<= 1) {
                s_  += __shfl_xor_sync(0xffffffffu, s_,  o);
                ss_ += __shfl_xor_sync(0xffffffffu, ss_, o);
            }
            if (cq == 0) {
                int row = warp_m + (sl >> 1) * 16 + (sl & 1) * 8 + R;
                float mu = s_ * (1.0f / DD);
                float ms = ss_ * (1.0f / DD);
                if (MODE == 0) {
                    smu[row] = mu;
                    srs[row] = rsqrtf(ms - mu * mu + 1e-5f);
                } else {
                    g_musel[m0 + row] = mu;
                    g_qsel[m0 + row]  = ms;
                }
            }
        }
    }

    // ---- epilogue ----
    if (MODE == 0) {
        __syncthreads();
        #pragma unroll
        for (int mt = 0; mt < 2; ++mt) {
            int mrow = warp_m + mt * 16 + R;
            float muA = smu[mrow],     rsA = srs[mrow];
            float muB = smu[mrow + 8], rsB = srs[mrow + 8];
            #pragma unroll
            for (int nt = 0; nt < 8; ++nt) {
                int n = warp_n + nt * 8 + 2 * cq;
                float2 cc1 = *(float2*)(sc1 + n);
                float2 cc2 = *(float2*)(sc2 + n);
                *(float2*)(sepi + mrow * ESTR + n) = make_float2(
                    gelu_f(rsA * acc[mt][nt][0] + cc1.x - muA * rsA * cc2.x),
                    gelu_f(rsA * acc[mt][nt][1] + cc1.y - muA * rsA * cc2.y));
                *(float2*)(sepi + (mrow + 8) * ESTR + n) = make_float2(
                    gelu_f(rsB * acc[mt][nt][2] + cc1.x - muB * rsB * cc2.x),
                    gelu_f(rsB * acc[mt][nt][3] + cc1.y - muB * rsB * cc2.y));
            }
        }
        __syncthreads();
        const int col = tid;
        #pragma unroll
        for (int rl = 0; rl < 15; ++rl) {
            int rg = r0 + rl;
            int s = (rg * TT) / TR - ts;
            int e = ((rg + 1) * TT + TR - 1) / TR - ts;
            float a = 0.0f;
            for (int t = s; t < e; ++t) a += sepi[t * ESTR + col];
            out[((size_t)((b_ * TR + rg) * JJ + j_)) * DD + col] = a / (float)(e - s);
        }
    } else {
        #pragma unroll
        for (int mt = 0; mt < 2; ++mt) {
            int mrow = m0 + warp_m + mt * 16 + R;
            #pragma unroll
            for (int nt = 0; nt < 8; ++nt) {
                int n = warp_n + nt * 8 + 2 * cq;
                *(float2*)(out + (size_t)mrow * DD + n) =
                    make_float2(acc[mt][nt][0], acc[mt][nt][1]);
                *(float2*)(out + (size_t)(mrow + 8) * DD + n) =
                    make_float2(acc[mt][nt][2], acc[mt][nt][3]);
            }
        }
    }
}

// ---------------- pooled mean over J ----------------
__global__ __launch_bounds__(256) void pooled_mean_kernel() {
    int id = blockIdx.x;
    int c = threadIdx.x;
    float acc = 0.0f;
    #pragma unroll
    for (int j = 0; j < JJ; ++j)
        acc += g_xd[((size_t)(id * JJ + j)) * DD + c];
    g_pm[(size_t)id * DD + c] = acc * (1.0f / JJ);
}

// ---------------- scorer: grid BB*4, each block 15 r's, w1 in smem ----------------
__global__ __launch_bounds__(128) void scorer_score(
    const float* __restrict__ w1, const float* __restrict__ b1,
    const float* __restrict__ w2, const float* __restrict__ b2)
{
    extern __shared__ float sw1[];
    __shared__ float spm[DD];
    __shared__ float red[DH];
    int b = blockIdx.x >> 2, grp = blockIdx.x & 3;
    int tid = threadIdx.x;

    #pragma unroll 8
    for (int i = tid; i < DD * DH / 4; i += 128)
        *(float4*)(sw1 + i * 4) = *(const float4*)(w1 + i * 4);
    float b1v = b1[tid];
    float w2v = w2[tid];
    float b2v = b2[0];
    __syncthreads();

    for (int rl = 0; rl < 15; ++rl) {
        int r = grp * 15 + rl;
        spm[tid]       = g_pm[((size_t)(b * TR + r)) * DD + tid];
        spm[tid + 128] = g_pm[((size_t)(b * TR + r)) * DD + tid + 128];
        __syncthreads();
        float acc = b1v;
        #pragma unroll 8
        for (int c = 0; c < DD; ++c)
            acc = fmaf(spm[c], sw1[c * DH + tid], acc);
        red[tid] = gelu_f(acc) * w2v;
        __syncthreads();
        #pragma unroll
        for (int s = 64; s > 0; s >>= 1) {
            if (tid < s) red[tid] += red[tid + s];
            __syncthreads();
        }
        if (tid == 0)
            g_score[b * TR + r] = 1.0f / (1.0f + expf(-(red[0] + b2v)));
        __syncthreads();
    }
}

// ---------------- top-k selection ----------------
__global__ __launch_bounds__(64) void topk_kernel() {
    __shared__ float sc[TR];
    __shared__ int sel[TR];
    int b = blockIdx.x, tid = threadIdx.x;
    if (tid < TR) sc[tid] = g_score[b * TR + tid];
    __syncthreads();
    if (tid < TR) {
        float s = sc[tid];
        int rank = 0;
        for (int q = 0; q < TR; ++q) {
            float sq = sc[q];
            rank += (sq > s) || (sq == s && q < tid);
        }
        sel[tid] = (rank < KSEL) ? 1 : 0;
    }
    __syncthreads();
    if (tid == 0) {
        int pos = 0;
        for (int r = 0; r < TR; ++r)
            if (sel[r]) g_topidx[b * KSEL + (pos++)] = r;
    }
}

// ---------------- cross-dot: E[xd_sel[p] * xd_sel[p+1]] ----------------
__global__ __launch_bounds__(256) void crossdot_kernel() {
    int id = blockIdx.x * 8 + (threadIdx.x >> 5);
    int lane = threadIdx.x & 31;
    if (id >= BB * (KSEL - 1) * JJ) return;
    int j = id % JJ;
    int p = (id / JJ) % (KSEL - 1);
    int b = id / (JJ * (KSEL - 1));
    int i0 = g_topidx[b * KSEL + p];
    int i1 = g_topidx[b * KSEL + p + 1];
    const float* r0 = g_xd + (size_t)((b * TR + i0) * JJ + j) * DD;
    const float* r1 = g_xd + (size_t)((b * TR + i1) * JJ + j) * DD;
    float s = 0.0f;
    #pragma unroll
    for (int h = 0; h < 2; ++h) {
        int c = h * 128 + lane * 4;
        float4 a = *(const float4*)(r0 + c);
        float4 d = *(const float4*)(r1 + c);
        s += a.x*d.x + a.y*d.y + a.z*d.z + a.w*d.w;
    }
    #pragma unroll
    for (int o = 16; o > 0; o >>= 1)
        s += __shfl_xor_sync(0xffffffffu, s, o);
    if (lane == 0) g_q01[id] = s * (1.0f / DD);
}

// ---------------- final epilogue: lerp(Y) affine + gelu + residual ----------------
__global__ __launch_bounds__(256) void epilogue_e(const float* __restrict__ X,
                                                  float* __restrict__ out) {
    int m = blockIdx.x * 8 + (threadIdx.x >> 5);
    int lane = threadIdx.x & 31;
    int b = m / TJ, rem = m % TJ;
    int t = rem / JJ, j = rem % JJ;

    float src = (t + 0.5f) * (float)(30.0 / 243.0) - 0.5f;
    src = fminf(fmaxf(src, 0.0f), (float)(KSEL - 1));
    int x0 = (int)src;
    int x1 = min(x0 + 1, KSEL - 1);
    float w = src - (float)x0;

    int ys0 = (b * KSEL + x0) * JJ + j;
    int ys1 = (b * KSEL + x1) * JJ + j;
    float mu0 = g_musel[ys0], q0 = g_qsel[ys0];
    float mu1 = g_musel[ys1], q1 = g_qsel[ys1];
    float q01 = (x1 > x0) ? g_q01[(b * (KSEL - 1) + x0) * JJ + j] : q0;
    float iw = 1.0f - w;
    float mu = iw * mu0 + w * mu1;
    float es = iw * iw * q0 + 2.0f * w * iw * q01 + w * w * q1;
    float rs = rsqrtf(es - mu * mu + 1e-5f);
    float mrs = mu * rs;

    const float* y0 = g_Y + (size_t)ys0 * DD;
    const float* y1 = g_Y + (size_t)ys1 * DD;
    #pragma unroll
    for (int h = 0; h < 2; ++h) {
        int c = h * 128 + lane * 4;
        float4 a = *(const float4*)(y0 + c);
        float4 d = *(const float4*)(y1 + c);
        float4 cc1 = *(const float4*)(g_c1op + c);
        float4 cc2 = *(const float4*)(g_c2op + c);
        float4 xr = *(const float4*)(X + (size_t)m * DD + c);
        float4 o;
        o.x = gelu_f(rs * (a.x + (d.x - a.x) * w) + cc1.x - mrs * cc2.x) + xr.x;
        o.y = gelu_f(rs * (a.y + (d.y - a.y) * w) + cc1.y - mrs * cc2.y) + xr.y;
        o.z = gelu_f(rs * (a.z + (d.z - a.z) * w) + cc1.z - mrs * cc2.z) + xr.z;
        o.w = gelu_f(rs * (a.w + (d.w - a.w) * w) + cc1.w - mrs * cc2.w) + xr.w;
        *(float4*)(out + (size_t)m * DD + c) = o;
    }
}

// ---------------- launch ----------------
#define SMEM_SC (DD * DH * 4)

extern "C" void kernel_launch(void* const* d_in, const int* in_sizes, int n_in,
                              void* d_out, int out_size) {
    const float* x       = (const float*)d_in[0];
    const float* fp_g    = (const float*)d_in[1];
    const float* fp_b    = (const float*)d_in[2];
    const float* fp_w    = (const float*)d_in[3];
    const float* fp_bias = (const float*)d_in[4];
    const float* sc_w1   = (const float*)d_in[5];
    const float* sc_b1   = (const float*)d_in[6];
    const float* sc_w2   = (const float*)d_in[7];
    const float* sc_b2   = (const float*)d_in[8];
    const float* op_g    = (const float*)d_in[9];
    const float* op_b    = (const float*)d_in[10];
    const float* op_w    = (const float*)d_in[11];
    const float* op_bias = (const float*)d_in[12];
    float* out = (float*)d_out;

    float *xd_ptr, *y_ptr, *c1fp, *c2fp, *c1op, *c2op;
    __nv_bfloat16 *w0h, *w0l, *w1h, *w1l;
    cudaGetSymbolAddress((void**)&xd_ptr, g_xd);
    cudaGetSymbolAddress((void**)&y_ptr, g_Y);
    cudaGetSymbolAddress((void**)&c1fp, g_c1fp);
    cudaGetSymbolAddress((void**)&c2fp, g_c2fp);
    cudaGetSymbolAddress((void**)&c1op, g_c1op);
    cudaGetSymbolAddress((void**)&c2op, g_c2op);
    cudaGetSymbolAddress((void**)&w0h, g_w0h);
    cudaGetSymbolAddress((void**)&w0l, g_w0l);
    cudaGetSymbolAddress((void**)&w1h, g_w1h);
    cudaGetSymbolAddress((void**)&w1l, g_w1l);

    cudaFuncSetAttribute(gemm_f<0>, cudaFuncAttributeMaxDynamicSharedMemorySize, SMEM_G);
    cudaFuncSetAttribute(gemm_f<1>, cudaFuncAttributeMaxDynamicSharedMemorySize, SMEM_G);
    cudaFuncSetAttribute(scorer_score, cudaFuncAttributeMaxDynamicSharedMemorySize, SMEM_SC);

    prep_w2<<<512, 256>>>(fp_w, fp_g, op_w, op_g, w0h, w0l, w1h, w1l);
    calc_c2<<<512, 256>>>(fp_w, fp_b, fp_g, fp_bias, op_w, op_b, op_g, op_bias,
                          c1fp, c2fp, c1op, c2op);
    gemm_f<0><<<BB * JJ * 4, 256, SMEM_G>>>(x, w0h, w0l, c1fp, c2fp, xd_ptr);
    pooled_mean_kernel<<<BB * TR, 256>>>();
    scorer_score<<<BB * 4, 128, SMEM_SC>>>(sc_w1, sc_b1, sc_w2, sc_b2);
    topk_kernel<<<BB, 64>>>();
    gemm_f<1><<<YROWS / 64, 256, SMEM_G>>>(x, w1h, w1l, c1op, c2op, y_ptr);
    crossdot_kernel<<<(BB * (KSEL - 1) * JJ + 7) / 8, 256>>>();
    epilogue_e<<<MROWS / 8, 256>>>(x, out);
}

// round 12
// speedup vs baseline: 2.0697x; 1.1868x over previous
#include <cuda_runtime.h>
#include <cuda_fp16.h>
#include <math.h>
#include <stdint.h>

// ---------------- problem constants ----------------
#define BB 64
#define TT 243
#define JJ 17
#define DD 256
#define DH 128
#define TR 60
#define KSEL 30
#define KSJ (KSEL*JJ)          // 510
#define YROWS (BB*KSJ)         // 32640
#define MROWS (BB*TT*JJ)       // 264384
#define TJ (TT*JJ)             // 4131

// ---------------- scratch ----------------
__device__ float g_xd[(size_t)BB*TR*JJ*DD];
__device__ float g_pm[(size_t)BB*TR*DD];
__device__ float g_score[BB*TR];
__device__ int   g_topidx[BB*KSEL];
__device__ float g_Y[(size_t)YROWS*DD];
__device__ float g_musel[YROWS], g_qsel[YROWS];
__device__ float g_q01[BB*(KSEL-1)*JJ];
__device__ float g_c1fp[DD], g_c2fp[DD];
__device__ float g_c1op[DD], g_c2op[DD];
__device__ __half g_w0f[DD*DD];     // (fp_g ⊙ fp_w)^T fp16
__device__ __half g_w1f[DD*DD];     // (op_g ⊙ op_w)^T fp16

__device__ __forceinline__ float gelu_f(float x) {
    return 0.5f * x * (1.0f + erff(x * 0.70710678118654752f));
}
__device__ __forceinline__ uint32_t smem_u32(const void* p) {
    uint32_t a;
    asm("{ .reg .u64 t; cvta.to.shared.u64 t, %1; cvt.u32.u64 %0, t; }" : "=r"(a) : "l"(p));
    return a;
}
__device__ __forceinline__ void mma_f16(float* d, const uint32_t* a,
                                        uint32_t b0, uint32_t b1) {
    asm volatile(
        "mma.sync.aligned.m16n8k16.row.col.f32.f16.f16.f32 "
        "{%0,%1,%2,%3}, {%4,%5,%6,%7}, {%8,%9}, {%0,%1,%2,%3};"
        : "+f"(d[0]), "+f"(d[1]), "+f"(d[2]), "+f"(d[3])
        : "r"(a[0]), "r"(a[1]), "r"(a[2]), "r"(a[3]), "r"(b0), "r"(b1));
}
#define LDSM4(r, addr) \
    asm volatile("ldmatrix.sync.aligned.m8n8.x4.shared.b16 {%0,%1,%2,%3}, [%4];" \
        : "=r"((r)[0]), "=r"((r)[1]), "=r"((r)[2]), "=r"((r)[3]) : "r"(addr))
#define CP_ASYNC(dst, src) asm volatile("cp.async.cg.shared.global [%0], [%1], 16;" :: "r"(dst), "l"(src))
#define CP_COMMIT()        asm volatile("cp.async.commit_group;" ::: "memory")
#define CP_WAIT(n)         asm volatile("cp.async.wait_group %0;" :: "n"(n) : "memory")

// smem geometry
#define RSTR 40
#define RAWB (64*RSTR)          // 2560 floats per raw A buffer
#define BSTR 20
#define BB_  (256*BSTR)         // 5120 u32 per B buffer (fp16, single)
#define HDR 832
// compute region: 2*RAWB + 2*BB_ = 15360 floats; epilogue stage needs 64*258 = 16512
#define SMEM_G ((HDR + 16512) * 4)   // 69376 B (covers both uses)
#define ESTR 258

// ---------------- prep: both weights, W' = gamma ⊙ W, transpose to fp16 ----------------
__global__ __launch_bounds__(256) void prep_w2(
    const float* __restrict__ W0, const float* __restrict__ g0,
    const float* __restrict__ W1, const float* __restrict__ g1,
    __half* __restrict__ W0f, __half* __restrict__ W1f)
{
    int which = blockIdx.x >> 8;
    int idx = (blockIdx.x & 255) * 256 + threadIdx.x;
    int k = idx >> 8, n = idx & 255;
    const float* W = which ? W1 : W0;
    const float* g = which ? g1 : g0;
    float w = W[idx] * g[k];
    (which ? W1f : W0f)[n * DD + k] = __float2half_rn(w);
}

// ---------------- prep: c1[n] = beta@W + bias[n], c2[n] = gamma@W (both) ----------------
__global__ __launch_bounds__(256) void calc_c2(
    const float* __restrict__ W0, const float* __restrict__ be0,
    const float* __restrict__ ga0, const float* __restrict__ bi0,
    const float* __restrict__ W1, const float* __restrict__ be1,
    const float* __restrict__ ga1, const float* __restrict__ bi1,
    float* __restrict__ c1a, float* __restrict__ c2a,
    float* __restrict__ c1b, float* __restrict__ c2b)
{
    __shared__ float r1[256], r2[256];
    int which = blockIdx.x >> 8;
    int n = blockIdx.x & 255, k = threadIdx.x;
    const float* W = which ? W1 : W0;
    float w = W[k * DD + n];
    r1[k] = (which ? be1 : be0)[k] * w;
    r2[k] = (which ? ga1 : ga0)[k] * w;
    __syncthreads();
    #pragma unroll
    for (int s = 128; s > 0; s >>= 1) {
        if (k < s) { r1[k] += r1[k + s]; r2[k] += r2[k + s]; }
        __syncthreads();
    }
    if (k == 0) {
        (which ? c1b : c1a)[n] = r1[0] + (which ? bi1 : bi0)[n];
        (which ? c2b : c2a)[n] = r2[0];
    }
}

// ---------------- fp16 x2 mma GEMM: A split hi/lo in regs, B single fp16 ----------------
// MODE 0: A = raw x t-slab of (b,j); epilogue gelu(affine) + pool -> g_xd
// MODE 1: A = selected xd rows; plain Y store + row stats
template <int MODE>
__global__ __launch_bounds__(256, 2) void gemm_f(
    const float* __restrict__ X,
    const __half* __restrict__ Wf,
    const float* __restrict__ c1, const float* __restrict__ c2,
    float* __restrict__ out)
{
    extern __shared__ float smem[];
    float* sc1 = smem;
    float* sc2 = smem + 256;
    float* smu = smem + 512;
    float* srs = smem + 576;
    float* sAr = smem + HDR;                            // [2][64][RSTR] raw fp32
    uint32_t* sB = (uint32_t*)(smem + HDR + 2 * RAWB);  // [2 buf][256][BSTR] fp16
    float* sepi = smem + HDR;

    const int tid  = threadIdx.x;
    const int wid  = tid >> 5;
    const int lane = tid & 31;
    const int warp_m = (wid & 1) * 32;
    const int warp_n = (wid >> 1) * 64;
    const int R  = lane >> 2;
    const int cq = lane & 3;
    const int aq = tid & 7;

    int b_ = 0, j_ = 0, ts = 0, rows = 64, r0 = 0, m0 = 0;
    if (MODE == 0) {
        int bj = blockIdx.x >> 2, tile = blockIdx.x & 3;
        b_ = bj / JJ; j_ = bj % JJ;
        r0 = tile * 15;
        ts = (r0 * TT) / TR;
        int te = ((r0 + 15) * TT + TR - 1) / TR;
        rows = te - ts;
        sc1[tid] = c1[tid];
        sc2[tid] = c2[tid];
    } else {
        m0 = blockIdx.x * 64;
    }

    int offA0[2];
    #pragma unroll
    for (int it = 0; it < 2; ++it) {
        int row = (tid >> 3) + it * 32;
        if (MODE == 0) {
            int rc = min(row, rows - 1);
            offA0[it] = ((b_ * TT + ts + rc) * JJ + j_) * DD + aq * 4;
        } else {
            int yrow = m0 + row;
            int b = yrow / KSJ;
            int rem = yrow % KSJ;
            int s = rem / JJ, j = rem % JJ;
            offA0[it] = ((b * TR + g_topidx[b * KSEL + s]) * JJ + j) * DD + aq * 4;
        }
    }
    const float* Asrc = (MODE == 0) ? X : &g_xd[0];
    const bool stats_on = (wid < 2);
    float sAc[4] = {0,0,0,0}, ssAc[4] = {0,0,0,0};

    float acc[2][8][4];
    #pragma unroll
    for (int i = 0; i < 2; i++)
        #pragma unroll
        for (int j = 0; j < 8; j++)
            #pragma unroll
            for (int q = 0; q < 4; q++) acc[i][j][q] = 0.0f;

    const uint32_t bBase = smem_u32(sB) +
        4 * ((warp_n + (lane & 7) + ((lane >> 4) & 1) * 8) * BSTR + ((lane >> 3) & 1) * 4);

    auto stageA = [&](int kt, int buf) {
        #pragma unroll
        for (int it = 0; it < 2; ++it) {
            int row = (tid >> 3) + it * 32;
            uint32_t d = smem_u32(sAr + buf * RAWB + row * RSTR + aq * 4);
            CP_ASYNC(d, Asrc + offA0[it] + kt);
        }
    };
    auto stageB = [&](int kt, int buf) {
        #pragma unroll
        for (int it = 0; it < 4; ++it) {
            int f = tid + it * 256;
            int n = f >> 2;
            int q = f & 3;
            uint32_t dh = smem_u32(sB + buf * BB_ + n * BSTR + q * 4);
            CP_ASYNC(dh, Wf + (size_t)n * DD + kt + q * 8);
        }
    };

    // ---- prologue ----
    stageA(0, 0); stageB(0, 0);
    CP_COMMIT();
    CP_WAIT(0);
    __syncthreads();

    // ---- main loop: one barrier per chunk ----
    #pragma unroll 1
    for (int c = 0; c < 8; ++c) {
        const int buf = c & 1;
        if (c < 7) { stageA((c + 1) * 32, buf ^ 1); stageB((c + 1) * 32, buf ^ 1); CP_COMMIT(); }

        #pragma unroll
        for (int ks = 0; ks < 2; ++ks) {
            // build A hi/lo fp16 fragments from raw smem
            uint32_t ah[2][4], al[2][4];
            #pragma unroll
            for (int mt = 0; mt < 2; ++mt) {
                #pragma unroll
                for (int pr = 0; pr < 2; ++pr) {
                    int row = warp_m + mt * 16 + pr * 8 + R;
                    const float* bp = sAr + buf * RAWB + row * RSTR + ks * 16 + 2 * cq;
                    float2 v0 = *(const float2*)bp;
                    float2 v1 = *(const float2*)(bp + 8);
                    if (stats_on) {
                        int sl = mt * 2 + pr;
                        sAc[sl]  += v0.x + v0.y + v1.x + v1.y;
                        ssAc[sl] += v0.x*v0.x + v0.y*v0.y + v1.x*v1.x + v1.y*v1.y;
                    }
                    __half2 h0 = __floats2half2_rn(v0.x, v0.y);
                    __half2 h1 = __floats2half2_rn(v1.x, v1.y);
                    float2 hf0 = __half22float2(h0);
                    float2 hf1 = __half22float2(h1);
                    __half2 l0 = __floats2half2_rn(v0.x - hf0.x, v0.y - hf0.y);
                    __half2 l1 = __floats2half2_rn(v1.x - hf1.x, v1.y - hf1.y);
                    ah[mt][pr]     = *(uint32_t*)&h0;
                    ah[mt][2 + pr] = *(uint32_t*)&h1;
                    al[mt][pr]     = *(uint32_t*)&l0;
                    al[mt][2 + pr] = *(uint32_t*)&l1;
                }
            }
            // B fragments + MMAs (2 terms: ah*b, al*b)
            #pragma unroll
            for (int p = 0; p < 4; ++p) {
                uint32_t bf[4];
                LDSM4(bf, bBase + 4 * (buf * BB_ + p * 16 * BSTR + ks * 8));
                const int n0 = 2 * p, n1 = 2 * p + 1;
                mma_f16(acc[0][n0], ah[0], bf[0], bf[1]);
                mma_f16(acc[1][n0], ah[1], bf[0], bf[1]);
                mma_f16(acc[0][n1], ah[0], bf[2], bf[3]);
                mma_f16(acc[1][n1], ah[1], bf[2], bf[3]);
                mma_f16(acc[0][n0], al[0], bf[0], bf[1]);
                mma_f16(acc[1][n0], al[1], bf[0], bf[1]);
                mma_f16(acc[0][n1], al[0], bf[2], bf[3]);
                mma_f16(acc[1][n1], al[1], bf[2], bf[3]);
            }
        }
        if (c < 7) CP_WAIT(0);
        __syncthreads();
    }

    // ---- finalize row stats (warps 0,1 own rows 0-63) ----
    if (stats_on) {
        #pragma unroll
        for (int sl = 0; sl < 4; ++sl) {
            float s_ = sAc[sl], ss_ = ssAc[sl];
            #pragma unroll
            for (int o = 1; o <= 2; o <<= 1) {
                s_  += __shfl_xor_sync(0xffffffffu, s_,  o);
                ss_ += __shfl_xor_sync(0xffffffffu, ss_, o);
            }
            if (cq == 0) {
                int row = warp_m + (sl >> 1) * 16 + (sl & 1) * 8 + R;
                float mu = s_ * (1.0f / DD);
                float ms = ss_ * (1.0f / DD);
                if (MODE == 0) {
                    smu[row] = mu;
                    srs[row] = rsqrtf(ms - mu * mu + 1e-5f);
                } else {
                    g_musel[m0 + row] = mu;
                    g_qsel[m0 + row]  = ms;
                }
            }
        }
    }

    // ---- epilogue ----
    if (MODE == 0) {
        __syncthreads();
        #pragma unroll
        for (int mt = 0; mt < 2; ++mt) {
            int mrow = warp_m + mt * 16 + R;
            float muA = smu[mrow],     rsA = srs[mrow];
            float muB = smu[mrow + 8], rsB = srs[mrow + 8];
            #pragma unroll
            for (int nt = 0; nt < 8; ++nt) {
                int n = warp_n + nt * 8 + 2 * cq;
                float2 cc1 = *(float2*)(sc1 + n);
                float2 cc2 = *(float2*)(sc2 + n);
                *(float2*)(sepi + mrow * ESTR + n) = make_float2(
                    gelu_f(rsA * acc[mt][nt][0] + cc1.x - muA * rsA * cc2.x),
                    gelu_f(rsA * acc[mt][nt][1] + cc1.y - muA * rsA * cc2.y));
                *(float2*)(sepi + (mrow + 8) * ESTR + n) = make_float2(
                    gelu_f(rsB * acc[mt][nt][2] + cc1.x - muB * rsB * cc2.x),
                    gelu_f(rsB * acc[mt][nt][3] + cc1.y - muB * rsB * cc2.y));
            }
        }
        __syncthreads();
        const int col = tid;
        #pragma unroll
        for (int rl = 0; rl < 15; ++rl) {
            int rg = r0 + rl;
            int s = (rg * TT) / TR - ts;
            int e = ((rg + 1) * TT + TR - 1) / TR - ts;
            float a = 0.0f;
            for (int t = s; t < e; ++t) a += sepi[t * ESTR + col];
            out[((size_t)((b_ * TR + rg) * JJ + j_)) * DD + col] = a / (float)(e - s);
        }
    } else {
        #pragma unroll
        for (int mt = 0; mt < 2; ++mt) {
            int mrow = m0 + warp_m + mt * 16 + R;
            #pragma unroll
            for (int nt = 0; nt < 8; ++nt) {
                int n = warp_n + nt * 8 + 2 * cq;
                *(float2*)(out + (size_t)mrow * DD + n) =
                    make_float2(acc[mt][nt][0], acc[mt][nt][1]);
                *(float2*)(out + (size_t)(mrow + 8) * DD + n) =
                    make_float2(acc[mt][nt][2], acc[mt][nt][3]);
            }
        }
    }
}

// ---------------- pooled mean over J ----------------
__global__ __launch_bounds__(256) void pooled_mean_kernel() {
    int id = blockIdx.x;
    int c = threadIdx.x;
    float acc = 0.0f;
    #pragma unroll
    for (int j = 0; j < JJ; ++j)
        acc += g_xd[((size_t)(id * JJ + j)) * DD + c];
    g_pm[(size_t)id * DD + c] = acc * (1.0f / JJ);
}

// ---------------- scorer: grid BB*4, each block 15 r's, w1 in smem ----------------
__global__ __launch_bounds__(128) void scorer_score(
    const float* __restrict__ w1, const float* __restrict__ b1,
    const float* __restrict__ w2, const float* __restrict__ b2)
{
    extern __shared__ float sw1[];
    __shared__ float spm[DD];
    __shared__ float red[DH];
    int b = blockIdx.x >> 2, grp = blockIdx.x & 3;
    int tid = threadIdx.x;

    #pragma unroll 8
    for (int i = tid; i < DD * DH / 4; i += 128)
        *(float4*)(sw1 + i * 4) = *(const float4*)(w1 + i * 4);
    float b1v = b1[tid];
    float w2v = w2[tid];
    float b2v = b2[0];
    __syncthreads();

    for (int rl = 0; rl < 15; ++rl) {
        int r = grp * 15 + rl;
        spm[tid]       = g_pm[((size_t)(b * TR + r)) * DD + tid];
        spm[tid + 128] = g_pm[((size_t)(b * TR + r)) * DD + tid + 128];
        __syncthreads();
        float acc = b1v;
        #pragma unroll 8
        for (int c = 0; c < DD; ++c)
            acc = fmaf(spm[c], sw1[c * DH + tid], acc);
        red[tid] = gelu_f(acc) * w2v;
        __syncthreads();
        #pragma unroll
        for (int s = 64; s > 0; s >>= 1) {
            if (tid < s) red[tid] += red[tid + s];
            __syncthreads();
        }
        if (tid == 0)
            g_score[b * TR + r] = 1.0f / (1.0f + expf(-(red[0] + b2v)));
        __syncthreads();
    }
}

// ---------------- top-k selection ----------------
__global__ __launch_bounds__(64) void topk_kernel() {
    __shared__ float sc[TR];
    __shared__ int sel[TR];
    int b = blockIdx.x, tid = threadIdx.x;
    if (tid < TR) sc[tid] = g_score[b * TR + tid];
    __syncthreads();
    if (tid < TR) {
        float s = sc[tid];
        int rank = 0;
        for (int q = 0; q < TR; ++q) {
            float sq = sc[q];
            rank += (sq > s) || (sq == s && q < tid);
        }
        sel[tid] = (rank < KSEL) ? 1 : 0;
    }
    __syncthreads();
    if (tid == 0) {
        int pos = 0;
        for (int r = 0; r < TR; ++r)
            if (sel[r]) g_topidx[b * KSEL + (pos++)] = r;
    }
}

// ---------------- cross-dot: E[xd_sel[p] * xd_sel[p+1]] ----------------
__global__ __launch_bounds__(256) void crossdot_kernel() {
    int id = blockIdx.x * 8 + (threadIdx.x >> 5);
    int lane = threadIdx.x & 31;
    if (id >= BB * (KSEL - 1) * JJ) return;
    int j = id % JJ;
    int p = (id / JJ) % (KSEL - 1);
    int b = id / (JJ * (KSEL - 1));
    int i0 = g_topidx[b * KSEL + p];
    int i1 = g_topidx[b * KSEL + p + 1];
    const float* r0 = g_xd + (size_t)((b * TR + i0) * JJ + j) * DD;
    const float* r1 = g_xd + (size_t)((b * TR + i1) * JJ + j) * DD;
    float s = 0.0f;
    #pragma unroll
    for (int h = 0; h < 2; ++h) {
        int c = h * 128 + lane * 4;
        float4 a = *(const float4*)(r0 + c);
        float4 d = *(const float4*)(r1 + c);
        s += a.x*d.x + a.y*d.y + a.z*d.z + a.w*d.w;
    }
    #pragma unroll
    for (int o = 16; o > 0; o >>= 1)
        s += __shfl_xor_sync(0xffffffffu, s, o);
    if (lane == 0) g_q01[id] = s * (1.0f / DD);
}

// ---------------- final epilogue: lerp(Y) affine + gelu + residual ----------------
__global__ __launch_bounds__(256) void epilogue_e(const float* __restrict__ X,
                                                  float* __restrict__ out) {
    int m = blockIdx.x * 8 + (threadIdx.x >> 5);
    int lane = threadIdx.x & 31;
    int b = m / TJ, rem = m % TJ;
    int t = rem / JJ, j = rem % JJ;

    float src = (t + 0.5f) * (float)(30.0 / 243.0) - 0.5f;
    src = fminf(fmaxf(src, 0.0f), (float)(KSEL - 1));
    int x0 = (int)src;
    int x1 = min(x0 + 1, KSEL - 1);
    float w = src - (float)x0;

    int ys0 = (b * KSEL + x0) * JJ + j;
    int ys1 = (b * KSEL + x1) * JJ + j;
    float mu0 = g_musel[ys0], q0 = g_qsel[ys0];
    float mu1 = g_musel[ys1], q1 = g_qsel[ys1];
    float q01 = (x1 > x0) ? g_q01[(b * (KSEL - 1) + x0) * JJ + j] : q0;
    float iw = 1.0f - w;
    float mu = iw * mu0 + w * mu1;
    float es = iw * iw * q0 + 2.0f * w * iw * q01 + w * w * q1;
    float rs = rsqrtf(es - mu * mu + 1e-5f);
    float mrs = mu * rs;

    const float* y0 = g_Y + (size_t)ys0 * DD;
    const float* y1 = g_Y + (size_t)ys1 * DD;
    #pragma unroll
    for (int h = 0; h < 2; ++h) {
        int c = h * 128 + lane * 4;
        float4 a = *(const float4*)(y0 + c);
        float4 d = *(const float4*)(y1 + c);
        float4 cc1 = *(const float4*)(g_c1op + c);
        float4 cc2 = *(const float4*)(g_c2op + c);
        float4 xr = *(const float4*)(X + (size_t)m * DD + c);
        float4 o;
        o.x = gelu_f(rs * (a.x + (d.x - a.x) * w) + cc1.x - mrs * cc2.x) + xr.x;
        o.y = gelu_f(rs * (a.y + (d.y - a.y) * w) + cc1.y - mrs * cc2.y) + xr.y;
        o.z = gelu_f(rs * (a.z + (d.z - a.z) * w) + cc1.z - mrs * cc2.z) + xr.z;
        o.w = gelu_f(rs * (a.w + (d.w - a.w) * w) + cc1.w - mrs * cc2.w) + xr.w;
        *(float4*)(out + (size_t)m * DD + c) = o;
    }
}

// ---------------- launch ----------------
#define SMEM_SC (DD * DH * 4)

extern "C" void kernel_launch(void* const* d_in, const int* in_sizes, int n_in,
                              void* d_out, int out_size) {
    const float* x       = (const float*)d_in[0];
    const float* fp_g    = (const float*)d_in[1];
    const float* fp_b    = (const float*)d_in[2];
    const float* fp_w    = (const float*)d_in[3];
    const float* fp_bias = (const float*)d_in[4];
    const float* sc_w1   = (const float*)d_in[5];
    const float* sc_b1   = (const float*)d_in[6];
    const float* sc_w2   = (const float*)d_in[7];
    const float* sc_b2   = (const float*)d_in[8];
    const float* op_g    = (const float*)d_in[9];
    const float* op_b    = (const float*)d_in[10];
    const float* op_w    = (const float*)d_in[11];
    const float* op_bias = (const float*)d_in[12];
    float* out = (float*)d_out;

    float *xd_ptr, *y_ptr, *c1fp, *c2fp, *c1op, *c2op;
    __half *w0f, *w1f;
    cudaGetSymbolAddress((void**)&xd_ptr, g_xd);
    cudaGetSymbolAddress((void**)&y_ptr, g_Y);
    cudaGetSymbolAddress((void**)&c1fp, g_c1fp);
    cudaGetSymbolAddress((void**)&c2fp, g_c2fp);
    cudaGetSymbolAddress((void**)&c1op, g_c1op);
    cudaGetSymbolAddress((void**)&c2op, g_c2op);
    cudaGetSymbolAddress((void**)&w0f, g_w0f);
    cudaGetSymbolAddress((void**)&w1f, g_w1f);

    cudaFuncSetAttribute(gemm_f<0>, cudaFuncAttributeMaxDynamicSharedMemorySize, SMEM_G);
    cudaFuncSetAttribute(gemm_f<1>, cudaFuncAttributeMaxDynamicSharedMemorySize, SMEM_G);
    cudaFuncSetAttribute(scorer_score, cudaFuncAttributeMaxDynamicSharedMemorySize, SMEM_SC);

    prep_w2<<<512, 256>>>(fp_w, fp_g, op_w, op_g, w0f, w1f);
    calc_c2<<<512, 256>>>(fp_w, fp_b, fp_g, fp_bias, op_w, op_b, op_g, op_bias,
                          c1fp, c2fp, c1op, c2op);
    gemm_f<0><<<BB * JJ * 4, 256, SMEM_G>>>(x, w0f, c1fp, c2fp, xd_ptr);
    pooled_mean_kernel<<<BB * TR, 256>>>();
    scorer_score<<<BB * 4, 128, SMEM_SC>>>(sc_w1, sc_b1, sc_w2, sc_b2);
    topk_kernel<<<BB, 64>>>();
    gemm_f<1><<<YROWS / 64, 256, SMEM_G>>>(x, w1f, c1op, c2op, y_ptr);
    crossdot_kernel<<<(BB * (KSEL - 1) * JJ + 7) / 8, 256>>>();
    epilogue_e<<<MROWS / 8, 256>>>(x, out);
}

// round 13
// speedup vs baseline: 2.3199x; 1.1209x over previous
#include <cuda_runtime.h>
#include <cuda_fp16.h>
#include <math.h>
#include <stdint.h>

// ---------------- problem constants ----------------
#define BB 64
#define TT 243
#define JJ 17
#define DD 256
#define DH 128
#define TR 60
#define KSEL 30
#define KSJ (KSEL*JJ)          // 510
#define YROWS (BB*KSJ)         // 32640
#define MROWS (BB*TT*JJ)       // 264384
#define TJ (TT*JJ)             // 4131

// ---------------- scratch ----------------
__device__ float g_xd[(size_t)BB*TR*JJ*DD];
__device__ float g_pm[(size_t)BB*TR*DD];
__device__ float g_score[BB*TR];
__device__ int   g_topidx[BB*KSEL];
__device__ float g_Y[(size_t)YROWS*DD];
__device__ float g_musel[YROWS], g_qsel[YROWS];
__device__ float g_q01[BB*(KSEL-1)*JJ];
__device__ float g_c1fp[DD], g_c2fp[DD];
__device__ float g_c1op[DD], g_c2op[DD];
__device__ __half g_w0f[DD*DD];     // (fp_g ⊙ fp_w)^T fp16
__device__ __half g_w1f[DD*DD];     // (op_g ⊙ op_w)^T fp16

__device__ __forceinline__ float gelu_f(float x) {
    return 0.5f * x * (1.0f + erff(x * 0.70710678118654752f));
}
__device__ __forceinline__ uint32_t smem_u32(const void* p) {
    uint32_t a;
    asm("{ .reg .u64 t; cvta.to.shared.u64 t, %1; cvt.u32.u64 %0, t; }" : "=r"(a) : "l"(p));
    return a;
}
__device__ __forceinline__ void mma_f16(float* d, const uint32_t* a,
                                        uint32_t b0, uint32_t b1) {
    asm volatile(
        "mma.sync.aligned.m16n8k16.row.col.f32.f16.f16.f32 "
        "{%0,%1,%2,%3}, {%4,%5,%6,%7}, {%8,%9}, {%0,%1,%2,%3};"
        : "+f"(d[0]), "+f"(d[1]), "+f"(d[2]), "+f"(d[3])
        : "r"(a[0]), "r"(a[1]), "r"(a[2]), "r"(a[3]), "r"(b0), "r"(b1));
}
#define LDSM4(r, addr) \
    asm volatile("ldmatrix.sync.aligned.m8n8.x4.shared.b16 {%0,%1,%2,%3}, [%4];" \
        : "=r"((r)[0]), "=r"((r)[1]), "=r"((r)[2]), "=r"((r)[3]) : "r"(addr))
#define CP_ASYNC(dst, src) asm volatile("cp.async.cg.shared.global [%0], [%1], 16;" :: "r"(dst), "l"(src))
#define CP_COMMIT()        asm volatile("cp.async.commit_group;" ::: "memory")
#define CP_WAIT(n)         asm volatile("cp.async.wait_group %0;" :: "n"(n) : "memory")

// smem geometry
#define RSTR 40
#define RAWB (64*RSTR)          // 2560 floats per raw A buffer
#define BSTR 20
#define BB_  (256*BSTR)         // 5120 u32 per B buffer (fp16, single)
#define HDR 832
// compute region: 2*RAWB + 2*BB_ = 15360 floats; epilogue stage needs 64*258 = 16512
#define SMEM_G ((HDR + 16512) * 4)   // 69376 B
#define ESTR 258

// ---------------- prep: both weights, W' = gamma ⊙ W, transpose to fp16 ----------------
__global__ __launch_bounds__(256) void prep_w2(
    const float* __restrict__ W0, const float* __restrict__ g0,
    const float* __restrict__ W1, const float* __restrict__ g1,
    __half* __restrict__ W0f, __half* __restrict__ W1f)
{
    int which = blockIdx.x >> 8;
    int idx = (blockIdx.x & 255) * 256 + threadIdx.x;
    int k = idx >> 8, n = idx & 255;
    const float* W = which ? W1 : W0;
    const float* g = which ? g1 : g0;
    float w = W[idx] * g[k];
    (which ? W1f : W0f)[n * DD + k] = __float2half_rn(w);
}

// ---------------- prep: c1[n] = beta@W + bias[n], c2[n] = gamma@W (both) ----------------
__global__ __launch_bounds__(256) void calc_c2(
    const float* __restrict__ W0, const float* __restrict__ be0,
    const float* __restrict__ ga0, const float* __restrict__ bi0,
    const float* __restrict__ W1, const float* __restrict__ be1,
    const float* __restrict__ ga1, const float* __restrict__ bi1,
    float* __restrict__ c1a, float* __restrict__ c2a,
    float* __restrict__ c1b, float* __restrict__ c2b)
{
    __shared__ float r1[256], r2[256];
    int which = blockIdx.x >> 8;
    int n = blockIdx.x & 255, k = threadIdx.x;
    const float* W = which ? W1 : W0;
    float w = W[k * DD + n];
    r1[k] = (which ? be1 : be0)[k] * w;
    r2[k] = (which ? ga1 : ga0)[k] * w;
    __syncthreads();
    #pragma unroll
    for (int s = 128; s > 0; s >>= 1) {
        if (k < s) { r1[k] += r1[k + s]; r2[k] += r2[k + s]; }
        __syncthreads();
    }
    if (k == 0) {
        (which ? c1b : c1a)[n] = r1[0] + (which ? bi1 : bi0)[n];
        (which ? c2b : c2a)[n] = r2[0];
    }
}

// ---------------- fp16 x1 mma GEMM: A fp16 in regs, B fp16 ----------------
// MODE 0: A = raw x t-slab of (b,j); epilogue gelu(affine) + pool -> g_xd
// MODE 1: A = selected xd rows; plain Y store + row stats
template <int MODE>
__global__ __launch_bounds__(256, 2) void gemm_f(
    const float* __restrict__ X,
    const __half* __restrict__ Wf,
    const float* __restrict__ c1, const float* __restrict__ c2,
    float* __restrict__ out)
{
    extern __shared__ float smem[];
    float* sc1 = smem;
    float* sc2 = smem + 256;
    float* smu = smem + 512;
    float* srs = smem + 576;
    float* sAr = smem + HDR;                            // [2][64][RSTR] raw fp32
    uint32_t* sB = (uint32_t*)(smem + HDR + 2 * RAWB);  // [2 buf][256][BSTR] fp16
    float* sepi = smem + HDR;

    const int tid  = threadIdx.x;
    const int wid  = tid >> 5;
    const int lane = tid & 31;
    const int warp_m = (wid & 1) * 32;
    const int warp_n = (wid >> 1) * 64;
    const int R  = lane >> 2;
    const int cq = lane & 3;
    const int aq = tid & 7;

    int b_ = 0, j_ = 0, ts = 0, rows = 64, r0 = 0, m0 = 0;
    if (MODE == 0) {
        int bj = blockIdx.x >> 2, tile = blockIdx.x & 3;
        b_ = bj / JJ; j_ = bj % JJ;
        r0 = tile * 15;
        ts = (r0 * TT) / TR;
        int te = ((r0 + 15) * TT + TR - 1) / TR;
        rows = te - ts;
        sc1[tid] = c1[tid];
        sc2[tid] = c2[tid];
    } else {
        m0 = blockIdx.x * 64;
    }

    int offA0[2];
    #pragma unroll
    for (int it = 0; it < 2; ++it) {
        int row = (tid >> 3) + it * 32;
        if (MODE == 0) {
            int rc = min(row, rows - 1);
            offA0[it] = ((b_ * TT + ts + rc) * JJ + j_) * DD + aq * 4;
        } else {
            int yrow = m0 + row;
            int b = yrow / KSJ;
            int rem = yrow % KSJ;
            int s = rem / JJ, j = rem % JJ;
            offA0[it] = ((b * TR + g_topidx[b * KSEL + s]) * JJ + j) * DD + aq * 4;
        }
    }
    const float* Asrc = (MODE == 0) ? X : &g_xd[0];
    const bool stats_on = (wid < 2);
    float sAc[4] = {0,0,0,0}, ssAc[4] = {0,0,0,0};

    float acc[2][8][4];
    #pragma unroll
    for (int i = 0; i < 2; i++)
        #pragma unroll
        for (int j = 0; j < 8; j++)
            #pragma unroll
            for (int q = 0; q < 4; q++) acc[i][j][q] = 0.0f;

    const uint32_t bBase = smem_u32(sB) +
        4 * ((warp_n + (lane & 7) + ((lane >> 4) & 1) * 8) * BSTR + ((lane >> 3) & 1) * 4);

    auto stageA = [&](int kt, int buf) {
        #pragma unroll
        for (int it = 0; it < 2; ++it) {
            int row = (tid >> 3) + it * 32;
            uint32_t d = smem_u32(sAr + buf * RAWB + row * RSTR + aq * 4);
            CP_ASYNC(d, Asrc + offA0[it] + kt);
        }
    };
    auto stageB = [&](int kt, int buf) {
        #pragma unroll
        for (int it = 0; it < 4; ++it) {
            int f = tid + it * 256;
            int n = f >> 2;
            int q = f & 3;
            uint32_t dh = smem_u32(sB + buf * BB_ + n * BSTR + q * 4);
            CP_ASYNC(dh, Wf + (size_t)n * DD + kt + q * 8);
        }
    };

    // ---- prologue ----
    stageA(0, 0); stageB(0, 0);
    CP_COMMIT();
    CP_WAIT(0);
    __syncthreads();

    // ---- main loop: one barrier per chunk ----
    #pragma unroll 1
    for (int c = 0; c < 8; ++c) {
        const int buf = c & 1;
        if (c < 7) { stageA((c + 1) * 32, buf ^ 1); stageB((c + 1) * 32, buf ^ 1); CP_COMMIT(); }

        #pragma unroll
        for (int ks = 0; ks < 2; ++ks) {
            // build A fp16 fragments from raw smem
            uint32_t ah[2][4];
            #pragma unroll
            for (int mt = 0; mt < 2; ++mt) {
                #pragma unroll
                for (int pr = 0; pr < 2; ++pr) {
                    int row = warp_m + mt * 16 + pr * 8 + R;
                    const float* bp = sAr + buf * RAWB + row * RSTR + ks * 16 + 2 * cq;
                    float2 v0 = *(const float2*)bp;
                    float2 v1 = *(const float2*)(bp + 8);
                    if (stats_on) {
                        int sl = mt * 2 + pr;
                        sAc[sl]  += v0.x + v0.y + v1.x + v1.y;
                        ssAc[sl] += v0.x*v0.x + v0.y*v0.y + v1.x*v1.x + v1.y*v1.y;
                    }
                    __half2 h0 = __floats2half2_rn(v0.x, v0.y);
                    __half2 h1 = __floats2half2_rn(v1.x, v1.y);
                    ah[mt][pr]     = *(uint32_t*)&h0;
                    ah[mt][2 + pr] = *(uint32_t*)&h1;
                }
            }
            // B fragments + MMAs (single term)
            #pragma unroll
            for (int p = 0; p < 4; ++p) {
                uint32_t bf[4];
                LDSM4(bf, bBase + 4 * (buf * BB_ + p * 16 * BSTR + ks * 8));
                const int n0 = 2 * p, n1 = 2 * p + 1;
                mma_f16(acc[0][n0], ah[0], bf[0], bf[1]);
                mma_f16(acc[1][n0], ah[1], bf[0], bf[1]);
                mma_f16(acc[0][n1], ah[0], bf[2], bf[3]);
                mma_f16(acc[1][n1], ah[1], bf[2], bf[3]);
            }
        }
        if (c < 7) CP_WAIT(0);
        __syncthreads();
    }

    // ---- finalize row stats (warps 0,1 own rows 0-63) ----
    if (stats_on) {
        #pragma unroll
        for (int sl = 0; sl < 4; ++sl) {
            float s_ = sAc[sl], ss_ = ssAc[sl];
            #pragma unroll
            for (int o = 1; o <= 2; o <<= 1) {
                s_  += __shfl_xor_sync(0xffffffffu, s_,  o);
                ss_ += __shfl_xor_sync(0xffffffffu, ss_, o);
            }
            if (cq == 0) {
                int row = warp_m + (sl >> 1) * 16 + (sl & 1) * 8 + R;
                float mu = s_ * (1.0f / DD);
                float ms = ss_ * (1.0f / DD);
                if (MODE == 0) {
                    smu[row] = mu;
                    srs[row] = rsqrtf(ms - mu * mu + 1e-5f);
                } else {
                    g_musel[m0 + row] = mu;
                    g_qsel[m0 + row]  = ms;
                }
            }
        }
    }

    // ---- epilogue ----
    if (MODE == 0) {
        __syncthreads();
        #pragma unroll
        for (int mt = 0; mt < 2; ++mt) {
            int mrow = warp_m + mt * 16 + R;
            float muA = smu[mrow],     rsA = srs[mrow];
            float muB = smu[mrow + 8], rsB = srs[mrow + 8];
            #pragma unroll
            for (int nt = 0; nt < 8; ++nt) {
                int n = warp_n + nt * 8 + 2 * cq;
                float2 cc1 = *(float2*)(sc1 + n);
                float2 cc2 = *(float2*)(sc2 + n);
                *(float2*)(sepi + mrow * ESTR + n) = make_float2(
                    gelu_f(rsA * acc[mt][nt][0] + cc1.x - muA * rsA * cc2.x),
                    gelu_f(rsA * acc[mt][nt][1] + cc1.y - muA * rsA * cc2.y));
                *(float2*)(sepi + (mrow + 8) * ESTR + n) = make_float2(
                    gelu_f(rsB * acc[mt][nt][2] + cc1.x - muB * rsB * cc2.x),
                    gelu_f(rsB * acc[mt][nt][3] + cc1.y - muB * rsB * cc2.y));
            }
        }
        __syncthreads();
        const int col = tid;
        #pragma unroll
        for (int rl = 0; rl < 15; ++rl) {
            int rg = r0 + rl;
            int s = (rg * TT) / TR - ts;
            int e = ((rg + 1) * TT + TR - 1) / TR - ts;
            float a = 0.0f;
            for (int t = s; t < e; ++t) a += sepi[t * ESTR + col];
            out[((size_t)((b_ * TR + rg) * JJ + j_)) * DD + col] = a / (float)(e - s);
        }
    } else {
        #pragma unroll
        for (int mt = 0; mt < 2; ++mt) {
            int mrow = m0 + warp_m + mt * 16 + R;
            #pragma unroll
            for (int nt = 0; nt < 8; ++nt) {
                int n = warp_n + nt * 8 + 2 * cq;
                *(float2*)(out + (size_t)mrow * DD + n) =
                    make_float2(acc[mt][nt][0], acc[mt][nt][1]);
                *(float2*)(out + (size_t)(mrow + 8) * DD + n) =
                    make_float2(acc[mt][nt][2], acc[mt][nt][3]);
            }
        }
    }
}

// ---------------- pooled mean over J ----------------
__global__ __launch_bounds__(256) void pooled_mean_kernel() {
    int id = blockIdx.x;
    int c = threadIdx.x;
    float acc = 0.0f;
    #pragma unroll
    for (int j = 0; j < JJ; ++j)
        acc += g_xd[((size_t)(id * JJ + j)) * DD + c];
    g_pm[(size_t)id * DD + c] = acc * (1.0f / JJ);
}

// ---------------- scorer: grid BB*4, each block 15 r's, w1 in smem ----------------
__global__ __launch_bounds__(128) void scorer_score(
    const float* __restrict__ w1, const float* __restrict__ b1,
    const float* __restrict__ w2, const float* __restrict__ b2)
{
    extern __shared__ float sw1[];
    __shared__ float spm[DD];
    __shared__ float red[DH];
    int b = blockIdx.x >> 2, grp = blockIdx.x & 3;
    int tid = threadIdx.x;

    #pragma unroll 8
    for (int i = tid; i < DD * DH / 4; i += 128)
        *(float4*)(sw1 + i * 4) = *(const float4*)(w1 + i * 4);
    float b1v = b1[tid];
    float w2v = w2[tid];
    float b2v = b2[0];
    __syncthreads();

    for (int rl = 0; rl < 15; ++rl) {
        int r = grp * 15 + rl;
        spm[tid]       = g_pm[((size_t)(b * TR + r)) * DD + tid];
        spm[tid + 128] = g_pm[((size_t)(b * TR + r)) * DD + tid + 128];
        __syncthreads();
        float acc = b1v;
        #pragma unroll 8
        for (int c = 0; c < DD; ++c)
            acc = fmaf(spm[c], sw1[c * DH + tid], acc);
        red[tid] = gelu_f(acc) * w2v;
        __syncthreads();
        #pragma unroll
        for (int s = 64; s > 0; s >>= 1) {
            if (tid < s) red[tid] += red[tid + s];
            __syncthreads();
        }
        if (tid == 0)
            g_score[b * TR + r] = 1.0f / (1.0f + expf(-(red[0] + b2v)));
        __syncthreads();
    }
}

// ---------------- top-k selection ----------------
__global__ __launch_bounds__(64) void topk_kernel() {
    __shared__ float sc[TR];
    __shared__ int sel[TR];
    int b = blockIdx.x, tid = threadIdx.x;
    if (tid < TR) sc[tid] = g_score[b * TR + tid];
    __syncthreads();
    if (tid < TR) {
        float s = sc[tid];
        int rank = 0;
        for (int q = 0; q < TR; ++q) {
            float sq = sc[q];
            rank += (sq > s) || (sq == s && q < tid);
        }
        sel[tid] = (rank < KSEL) ? 1 : 0;
    }
    __syncthreads();
    if (tid == 0) {
        int pos = 0;
        for (int r = 0; r < TR; ++r)
            if (sel[r]) g_topidx[b * KSEL + (pos++)] = r;
    }
}

// ---------------- cross-dot: E[xd_sel[p] * xd_sel[p+1]] ----------------
__global__ __launch_bounds__(256) void crossdot_kernel() {
    int id = blockIdx.x * 8 + (threadIdx.x >> 5);
    int lane = threadIdx.x & 31;
    if (id >= BB * (KSEL - 1) * JJ) return;
    int j = id % JJ;
    int p = (id / JJ) % (KSEL - 1);
    int b = id / (JJ * (KSEL - 1));
    int i0 = g_topidx[b * KSEL + p];
    int i1 = g_topidx[b * KSEL + p + 1];
    const float* r0 = g_xd + (size_t)((b * TR + i0) * JJ + j) * DD;
    const float* r1 = g_xd + (size_t)((b * TR + i1) * JJ + j) * DD;
    float s = 0.0f;
    #pragma unroll
    for (int h = 0; h < 2; ++h) {
        int c = h * 128 + lane * 4;
        float4 a = *(const float4*)(r0 + c);
        float4 d = *(const float4*)(r1 + c);
        s += a.x*d.x + a.y*d.y + a.z*d.z + a.w*d.w;
    }
    #pragma unroll
    for (int o = 16; o > 0; o >>= 1)
        s += __shfl_xor_sync(0xffffffffu, s, o);
    if (lane == 0) g_q01[id] = s * (1.0f / DD);
}

// ---------------- final epilogue: lerp(Y) affine + gelu + residual ----------------
__global__ __launch_bounds__(256) void epilogue_e(const float* __restrict__ X,
                                                  float* __restrict__ out) {
    int m = blockIdx.x * 8 + (threadIdx.x >> 5);
    int lane = threadIdx.x & 31;
    int b = m / TJ, rem = m % TJ;
    int t = rem / JJ, j = rem % JJ;

    float src = (t + 0.5f) * (float)(30.0 / 243.0) - 0.5f;
    src = fminf(fmaxf(src, 0.0f), (float)(KSEL - 1));
    int x0 = (int)src;
    int x1 = min(x0 + 1, KSEL - 1);
    float w = src - (float)x0;

    int ys0 = (b * KSEL + x0) * JJ + j;
    int ys1 = (b * KSEL + x1) * JJ + j;
    float mu0 = g_musel[ys0], q0 = g_qsel[ys0];
    float mu1 = g_musel[ys1], q1 = g_qsel[ys1];
    float q01 = (x1 > x0) ? g_q01[(b * (KSEL - 1) + x0) * JJ + j] : q0;
    float iw = 1.0f - w;
    float mu = iw * mu0 + w * mu1;
    float es = iw * iw * q0 + 2.0f * w * iw * q01 + w * w * q1;
    float rs = rsqrtf(es - mu * mu + 1e-5f);
    float mrs = mu * rs;

    const float* y0 = g_Y + (size_t)ys0 * DD;
    const float* y1 = g_Y + (size_t)ys1 * DD;
    #pragma unroll
    for (int h = 0; h < 2; ++h) {
        int c = h * 128 + lane * 4;
        float4 a = *(const float4*)(y0 + c);
        float4 d = *(const float4*)(y1 + c);
        float4 cc1 = *(const float4*)(g_c1op + c);
        float4 cc2 = *(const float4*)(g_c2op + c);
        float4 xr = *(const float4*)(X + (size_t)m * DD + c);
        float4 o;
        o.x = gelu_f(rs * (a.x + (d.x - a.x) * w) + cc1.x - mrs * cc2.x) + xr.x;
        o.y = gelu_f(rs * (a.y + (d.y - a.y) * w) + cc1.y - mrs * cc2.y) + xr.y;
        o.z = gelu_f(rs * (a.z + (d.z - a.z) * w) + cc1.z - mrs * cc2.z) + xr.z;
        o.w = gelu_f(rs * (a.w + (d.w - a.w) * w) + cc1.w - mrs * cc2.w) + xr.w;
        *(float4*)(out + (size_t)m * DD + c) = o;
    }
}

// ---------------- launch ----------------
#define SMEM_SC (DD * DH * 4)

extern "C" void kernel_launch(void* const* d_in, const int* in_sizes, int n_in,
                              void* d_out, int out_size) {
    const float* x       = (const float*)d_in[0];
    const float* fp_g    = (const float*)d_in[1];
    const float* fp_b    = (const float*)d_in[2];
    const float* fp_w    = (const float*)d_in[3];
    const float* fp_bias = (const float*)d_in[4];
    const float* sc_w1   = (const float*)d_in[5];
    const float* sc_b1   = (const float*)d_in[6];
    const float* sc_w2   = (const float*)d_in[7];
    const float* sc_b2   = (const float*)d_in[8];
    const float* op_g    = (const float*)d_in[9];
    const float* op_b    = (const float*)d_in[10];
    const float* op_w    = (const float*)d_in[11];
    const float* op_bias = (const float*)d_in[12];
    float* out = (float*)d_out;

    float *xd_ptr, *y_ptr, *c1fp, *c2fp, *c1op, *c2op;
    __half *w0f, *w1f;
    cudaGetSymbolAddress((void**)&xd_ptr, g_xd);
    cudaGetSymbolAddress((void**)&y_ptr, g_Y);
    cudaGetSymbolAddress((void**)&c1fp, g_c1fp);
    cudaGetSymbolAddress((void**)&c2fp, g_c2fp);
    cudaGetSymbolAddress((void**)&c1op, g_c1op);
    cudaGetSymbolAddress((void**)&c2op, g_c2op);
    cudaGetSymbolAddress((void**)&w0f, g_w0f);
    cudaGetSymbolAddress((void**)&w1f, g_w1f);

    cudaFuncSetAttribute(gemm_f<0>, cudaFuncAttributeMaxDynamicSharedMemorySize, SMEM_G);
    cudaFuncSetAttribute(gemm_f<1>, cudaFuncAttributeMaxDynamicSharedMemorySize, SMEM_G);
    cudaFuncSetAttribute(scorer_score, cudaFuncAttributeMaxDynamicSharedMemorySize, SMEM_SC);

    prep_w2<<<512, 256>>>(fp_w, fp_g, op_w, op_g, w0f, w1f);
    calc_c2<<<512, 256>>>(fp_w, fp_b, fp_g, fp_bias, op_w, op_b, op_g, op_bias,
                          c1fp, c2fp, c1op, c2op);
    gemm_f<0><<<BB * JJ * 4, 256, SMEM_G>>>(x, w0f, c1fp, c2fp, xd_ptr);
    pooled_mean_kernel<<<BB * TR, 256>>>();
    scorer_score<<<BB * 4, 128, SMEM_SC>>>(sc_w1, sc_b1, sc_w2, sc_b2);
    topk_kernel<<<BB, 64>>>();
    gemm_f<1><<<YROWS / 64, 256, SMEM_G>>>(x, w1f, c1op, c2op, y_ptr);
    crossdot_kernel<<<(BB * (KSEL - 1) * JJ + 7) / 8, 256>>>();
    epilogue_e<<<MROWS / 8, 256>>>(x, out);
}